// round 12
// baseline (speedup 1.0000x reference)
#include <cuda_runtime.h>
#include <cuda_fp16.h>
#include <cstdint>

#define NN   100000
#define NE   1600000
#define NPAD 100096          // 782 * 128
#define D_IN  128
#define D_HID 256
#define NTILES (NPAD / 128)  // 782

// ---------------- scratch (static __device__ arrays; device-code refs only) -
__device__ int   g_cnt[NN];
__device__ int   g_rowptr[NN + 1];
__device__ int   g_wp[NN];
__device__ __align__(8) int2 g_colw[NE];      // {src, __float_as_int(dinv[src])}
__device__ float g_dinv[NN];
__device__ int   g_bsum[128];
__device__ __align__(16) __half g_xh [(size_t)NN   * D_IN];   // x fp16
__device__ __align__(16) __half g_xa [(size_t)NPAD * D_IN];   // A@x fp16
__device__ __align__(16) __half g_h1 [(size_t)NPAD * D_HID];  // relu(xa@W1+b1)
__device__ __align__(16) __half g_y  [(size_t)NPAD * D_IN];   // h1@W2
__device__ __align__(16) __half g_w1h[D_IN * D_HID];
__device__ __align__(16) __half g_w2h[D_HID * D_IN];

// ---------------- fused convert + zero + histogram --------------------------
__global__ void k_prep(const float* __restrict__ x,
                       const float* __restrict__ W1,
                       const float* __restrict__ W2,
                       const int* __restrict__ ei) {
    int i = blockIdx.x * 256 + threadIdx.x;
    if (i < NN * 32) {
        float4 v = ((const float4*)x)[i];
        __half2 h0 = __floats2half2_rn(v.x, v.y);
        __half2 h1 = __floats2half2_rn(v.z, v.w);
        ((uint2*)g_xh)[i] = make_uint2(*(uint32_t*)&h0, *(uint32_t*)&h1);
    }
    if (i < NN) g_cnt[i] = 0;
    if (i < (D_IN * D_HID) / 4) {
        float4 a = ((const float4*)W1)[i];
        float4 b = ((const float4*)W2)[i];
        __half2 a0 = __floats2half2_rn(a.x, a.y), a1 = __floats2half2_rn(a.z, a.w);
        __half2 b0 = __floats2half2_rn(b.x, b.y), b1 = __floats2half2_rn(b.z, b.w);
        ((uint2*)g_w1h)[i] = make_uint2(*(uint32_t*)&a0, *(uint32_t*)&a1);
        ((uint2*)g_w2h)[i] = make_uint2(*(uint32_t*)&b0, *(uint32_t*)&b1);
    }
}
__global__ void k_hist(const int* __restrict__ ei) {
    int e = blockIdx.x * blockDim.x + threadIdx.x;
    if (e < NE) atomicAdd(&g_cnt[ei[NE + e]], 1);
}

// ---------------- CSR build ------------------------------------------------
__global__ void k_scan() {
    __shared__ int sh[1024];
    int i = blockIdx.x * 1024 + threadIdx.x;
    int v = (i < NN) ? g_cnt[i] : 0;
    sh[threadIdx.x] = v;
    __syncthreads();
    for (int off = 1; off < 1024; off <<= 1) {
        int t = (threadIdx.x >= off) ? sh[threadIdx.x - off] : 0;
        __syncthreads();
        sh[threadIdx.x] += t;
        __syncthreads();
    }
    if (i < NN) g_rowptr[i] = sh[threadIdx.x] - v;      // block-local exclusive
    if (threadIdx.x == 1023) g_bsum[blockIdx.x] = sh[1023];
}
__global__ void k_final() {    // block-sum scan folded in (redundant per block)
    __shared__ int shI[128];
    int t = threadIdx.x;
    if (t < 128) shI[t] = (t < 98) ? g_bsum[t] : 0;
    __syncthreads();
    for (int off = 1; off < 128; off <<= 1) {
        int u = (t >= off && t < 128) ? shI[t - off] : 0;
        __syncthreads();
        if (t < 128) shI[t] += u;
        __syncthreads();
    }
    int i = blockIdx.x * blockDim.x + t;
    if (i < NN) {
        int b = i >> 10;
        int base = (b == 0) ? 0 : shI[b - 1];
        int rp = g_rowptr[i] + base;
        g_rowptr[i] = rp;
        g_wp[i] = rp;
        g_dinv[i] = rsqrtf((float)(g_cnt[i] + 1));
    }
    if (i == 0) g_rowptr[NN] = NE;
}
__global__ void k_fill(const int* __restrict__ ei) {
    int e = blockIdx.x * blockDim.x + threadIdx.x;
    if (e < NE) {
        int s = ei[e];
        int d = ei[NE + e];
        int pos = atomicAdd(&g_wp[d], 1);
        g_colw[pos] = make_int2(s, __float_as_int(g_dinv[s]));
    }
}

// ---------------- aggregation: coalesced edge records, MLP-4 gather --------
__device__ __forceinline__ void fma_row(float4& acc, uint2 raw, float w) {
    float2 f0 = __half22float2(*(__half2*)&raw.x);
    float2 f1 = __half22float2(*(__half2*)&raw.y);
    acc.x += f0.x * w; acc.y += f0.y * w;
    acc.z += f1.x * w; acc.w += f1.y * w;
}

__device__ __forceinline__ float4 agg_row_h(const __half* __restrict__ X,
                                            int node, int lane) {
    const uint2* Xv = (const uint2*)X;
    float4 acc = make_float4(0.f, 0.f, 0.f, 0.f);
    int r0 = g_rowptr[node], r1 = g_rowptr[node + 1];
    float di = g_dinv[node];

    for (int base = r0; base < r1; base += 32) {
        int n = r1 - base; if (n > 32) n = 32;
        int2 cw = g_colw[base + (lane < n ? lane : 0)];   // coalesced
        int t = 0;
#pragma unroll 1
        for (; t + 4 <= n; t += 4) {                      // MLP=4: 4 indep LDGs
            int   s0 = __shfl_sync(0xffffffffu, cw.x, t);
            int   s1 = __shfl_sync(0xffffffffu, cw.x, t + 1);
            int   s2 = __shfl_sync(0xffffffffu, cw.x, t + 2);
            int   s3 = __shfl_sync(0xffffffffu, cw.x, t + 3);
            float w0 = __int_as_float(__shfl_sync(0xffffffffu, cw.y, t));
            float w1 = __int_as_float(__shfl_sync(0xffffffffu, cw.y, t + 1));
            float w2 = __int_as_float(__shfl_sync(0xffffffffu, cw.y, t + 2));
            float w3 = __int_as_float(__shfl_sync(0xffffffffu, cw.y, t + 3));
            uint2 q0 = Xv[(size_t)s0 * 32 + lane];
            uint2 q1 = Xv[(size_t)s1 * 32 + lane];
            uint2 q2 = Xv[(size_t)s2 * 32 + lane];
            uint2 q3 = Xv[(size_t)s3 * 32 + lane];
            fma_row(acc, q0, w0);
            fma_row(acc, q1, w1);
            fma_row(acc, q2, w2);
            fma_row(acc, q3, w3);
        }
#pragma unroll 1
        for (; t < n; t++) {
            int   s = __shfl_sync(0xffffffffu, cw.x, t);
            float w = __int_as_float(__shfl_sync(0xffffffffu, cw.y, t));
            fma_row(acc, Xv[(size_t)s * 32 + lane], w);
        }
    }
    uint2 raw = Xv[(size_t)node * 32 + lane];             // self-loop
    float2 f0 = __half22float2(*(__half2*)&raw.x);
    float2 f1 = __half22float2(*(__half2*)&raw.y);
    acc.x = (acc.x + f0.x * di) * di;
    acc.y = (acc.y + f0.y * di) * di;
    acc.z = (acc.z + f1.x * di) * di;
    acc.w = (acc.w + f1.y * di) * di;
    return acc;
}

__global__ void k_agg1() {
    int gw   = (blockIdx.x * blockDim.x + threadIdx.x) >> 5;
    int lane = threadIdx.x & 31;
    if (gw >= NN) return;
    float4 a = agg_row_h(g_xh, gw, lane);
    __half2 h0 = __floats2half2_rn(a.x, a.y);
    __half2 h1 = __floats2half2_rn(a.z, a.w);
    ((uint2*)g_xa)[(size_t)gw * 32 + lane] =
        make_uint2(*(uint32_t*)&h0, *(uint32_t*)&h1);
}

__global__ void k_agg2(float* __restrict__ out,
                       const float* __restrict__ bias,
                       const float* __restrict__ gamma,
                       const float* __restrict__ beta) {
    int gw   = (blockIdx.x * blockDim.x + threadIdx.x) >> 5;
    int lane = threadIdx.x & 31;
    if (gw >= NN) return;
    float4 acc = agg_row_h(g_y, gw, lane);

    float4 bb = ((const float4*)bias)[lane];
    acc.x += bb.x; acc.y += bb.y; acc.z += bb.z; acc.w += bb.w;

    float s = acc.x + acc.y + acc.z + acc.w;
#pragma unroll
    for (int o = 16; o; o >>= 1) s += __shfl_xor_sync(0xffffffffu, s, o);
    float mu = s * (1.f / 128.f);

    float d0 = acc.x - mu, d1 = acc.y - mu, d2 = acc.z - mu, d3 = acc.w - mu;
    float ss = d0 * d0 + d1 * d1 + d2 * d2 + d3 * d3;
#pragma unroll
    for (int o = 16; o; o >>= 1) ss += __shfl_xor_sync(0xffffffffu, ss, o);
    float rs = rsqrtf(ss * (1.f / 128.f) + 1e-5f);

    float4 g  = ((const float4*)gamma)[lane];
    float4 be = ((const float4*)beta)[lane];
    float4 o4;
    o4.x = d0 * rs * g.x + be.x;
    o4.y = d1 * rs * g.y + be.y;
    o4.z = d2 * rs * g.z + be.z;
    o4.w = d3 * rs * g.w + be.w;
    ((float4*)out)[(size_t)gw * 32 + lane] = o4;
}

// ---------------- fp16 mma.sync GEMM, cp.async staging ----------------------
__device__ __forceinline__ uint32_t smem_u32(const void* p) {
    uint32_t a;
    asm("{ .reg .u64 t; cvta.to.shared.u64 t, %1; cvt.u32.u64 %0, t; }"
        : "=r"(a) : "l"(p));
    return a;
}
#define CP_ASYNC16(dst, src) \
    asm volatile("cp.async.ca.shared.global [%0], [%1], 16;" \
                 :: "r"(dst), "l"(src) : "memory")
#define CP_COMMIT() asm volatile("cp.async.commit_group;" ::: "memory")
#define CP_WAIT(n)  asm volatile("cp.async.wait_group %0;" :: "n"(n) : "memory")

__device__ __forceinline__ void ldsm_x4(uint32_t* r, uint32_t addr) {
    asm volatile("ldmatrix.sync.aligned.m8n8.x4.shared.b16 {%0,%1,%2,%3}, [%4];"
        : "=r"(r[0]), "=r"(r[1]), "=r"(r[2]), "=r"(r[3]) : "r"(addr));
}
__device__ __forceinline__ void ldsm_x2t(uint32_t* r, uint32_t addr) {
    asm volatile("ldmatrix.sync.aligned.m8n8.x2.trans.shared.b16 {%0,%1}, [%2];"
        : "=r"(r[0]), "=r"(r[1]) : "r"(addr));
}
__device__ __forceinline__ void mma_f16(float* c, const uint32_t* a, const uint32_t* b) {
    asm volatile(
        "mma.sync.aligned.m16n8k16.row.col.f32.f16.f16.f32 "
        "{%0,%1,%2,%3}, {%4,%5,%6,%7}, {%8,%9}, {%0,%1,%2,%3};"
        : "+f"(c[0]), "+f"(c[1]), "+f"(c[2]), "+f"(c[3])
        : "r"(a[0]), "r"(a[1]), "r"(a[2]), "r"(a[3]), "r"(b[0]), "r"(b[1]));
}

template <int K, int NT, bool BIAS_RELU>
__device__ __forceinline__ void mma_body_h(const __half* __restrict__ A,
                                           const __half* __restrict__ B,
                                           const float* __restrict__ bias,
                                           __half* __restrict__ C) {
    __shared__ __align__(16) char Asm[2][8192];
    __shared__ __align__(16) char Bsm[2][8192];

    int tid = threadIdx.x, wid = tid >> 5, lane = tid & 31;
    int wm = wid >> 2, wn = wid & 3;          // 2x4 warps, 64x32 warp tile
    int rowBase = blockIdx.y * 128;
    int nBase   = blockIdx.x * 128;

    const __half* Ab = A + (size_t)rowBase * K;
    const __half* Bb = B + nBase;

    float acc[4][4][4];
#pragma unroll
    for (int i = 0; i < 4; i++)
#pragma unroll
        for (int j = 0; j < 4; j++)
#pragma unroll
            for (int q = 0; q < 4; q++) acc[i][j][q] = 0.f;

    uint32_t aSm[2] = {smem_u32(Asm[0]), smem_u32(Asm[1])};
    uint32_t bSm[2] = {smem_u32(Bsm[0]), smem_u32(Bsm[1])};

    auto stage = [&](int ch, int buf) {       // global -> smem via cp.async
#pragma unroll
        for (int it = 0; it < 2; it++) {
            int u = tid + it * 256;
            int r = u >> 2, c16 = u & 3;
            CP_ASYNC16(aSm[buf] + r * 64 + ((c16 ^ ((r >> 1) & 3)) << 4),
                       Ab + (size_t)r * K + ch * 32 + c16 * 8);
            int k = u >> 4, d16 = u & 15;
            CP_ASYNC16(bSm[buf] + k * 256 + ((d16 ^ (k & 7)) << 4),
                       Bb + (size_t)(ch * 32 + k) * NT + d16 * 8);
        }
        CP_COMMIT();
    };

    const int nch = K >> 5;
    stage(0, 0);

    int aG  = lane >> 3;
    int aRl = (aG & 1) * 8 + (lane & 7);
    int aCo = aG >> 1;
    int bK  = lane & 15;

#pragma unroll 1
    for (int ch = 0; ch < nch; ch++) {
        int buf = ch & 1;
        if (ch + 1 < nch) { stage(ch + 1, buf ^ 1); CP_WAIT(1); }
        else              { CP_WAIT(0); }
        __syncthreads();

#pragma unroll
        for (int ks = 0; ks < 2; ks++) {
            uint32_t af[4][4], bf[4][2];
#pragma unroll
            for (int i = 0; i < 4; i++) {
                int r   = (wm * 4 + i) * 16 + aRl;
                int c16 = ks * 2 + aCo;
                ldsm_x4(af[i], aSm[buf] + r * 64 + ((c16 ^ ((r >> 1) & 3)) << 4));
            }
#pragma unroll
            for (int j = 0; j < 4; j++) {
                int ntile = wn * 4 + j;
                int k = ks * 16 + bK;
                ldsm_x2t(bf[j], bSm[buf] + k * 256 + ((ntile ^ (k & 7)) << 4));
            }
#pragma unroll
            for (int i = 0; i < 4; i++)
#pragma unroll
                for (int j = 0; j < 4; j++)
                    mma_f16(acc[i][j], af[i], bf[j]);
        }
        __syncthreads();                      // buffer reuse guard
    }

    // epilogue (fp16 out)
    int crow = rowBase + wm * 64 + (lane >> 2);
    int ccol = nBase + wn * 32 + (lane & 3) * 2;
#pragma unroll
    for (int i = 0; i < 4; i++) {
#pragma unroll
        for (int j = 0; j < 4; j++) {
            int r0 = crow + i * 16, c0 = ccol + j * 8;
            float2 v0 = make_float2(acc[i][j][0], acc[i][j][1]);
            float2 v1 = make_float2(acc[i][j][2], acc[i][j][3]);
            if (BIAS_RELU) {
                float bx = bias[c0], by = bias[c0 + 1];
                v0.x = fmaxf(v0.x + bx, 0.f); v0.y = fmaxf(v0.y + by, 0.f);
                v1.x = fmaxf(v1.x + bx, 0.f); v1.y = fmaxf(v1.y + by, 0.f);
            }
            *(__half2*)&C[(size_t)r0 * NT + c0]       = __floats2half2_rn(v0.x, v0.y);
            *(__half2*)&C[(size_t)(r0 + 8) * NT + c0] = __floats2half2_rn(v1.x, v1.y);
        }
    }
}

__global__ __launch_bounds__(256)
void k_mma1(const float* __restrict__ b1) {
    mma_body_h<D_IN, D_HID, true>(g_xa, g_w1h, b1, g_h1);
}
__global__ __launch_bounds__(256)
void k_mma2() {
    mma_body_h<D_HID, D_IN, false>(g_h1, g_w2h, nullptr, g_y);
}

// ---------------- launch (kernel launches ONLY) -----------------------------
extern "C" void kernel_launch(void* const* d_in, const int* in_sizes, int n_in,
                              void* d_out, int out_size) {
    const float* x     = (const float*)d_in[0];
    const int*   ei    = (const int*)d_in[1];      // int32 edge_index [2, NE]
    const float* W1    = (const float*)d_in[2];
    const float* b1    = (const float*)d_in[3];
    const float* W2    = (const float*)d_in[4];
    const float* b2    = (const float*)d_in[5];
    const float* gamma = (const float*)d_in[6];
    const float* beta  = (const float*)d_in[7];
    float* out = (float*)d_out;

    k_prep <<<(NN * 32 + 255) / 256, 256>>>(x, W1, W2, ei);
    k_hist <<<(NE + 255) / 256, 256>>>(ei);
    k_scan <<<98, 1024>>>();
    k_final<<<(NN + 255) / 256, 256>>>();
    k_fill <<<(NE + 255) / 256, 256>>>(ei);

    // xa = A @ x  (fp16 gather, MLP-4, fp32 accum, fp16 out)
    k_agg1<<<(NN * 32) / 256, 256>>>();

    // h1 = relu(xa @ W1 + b1)   (fp16 mma + ldmatrix + cp.async)
    dim3 g1(D_HID / 128, NTILES);
    k_mma1<<<g1, 256>>>(b1);

    // y = h1 @ W2
    dim3 g2(D_IN / 128, NTILES);
    k_mma2<<<g2, 256>>>();

    // out = LayerNorm(A @ y + b2)
    k_agg2<<<(NN * 32) / 256, 256>>>(out, b2, gamma, beta);
}

// round 13
// speedup vs baseline: 1.0341x; 1.0341x over previous
#include <cuda_runtime.h>
#include <cuda_fp16.h>
#include <cstdint>

#define NN   100000
#define NE   1600000
#define NPAD 100096          // 782 * 128
#define D_IN  128
#define D_HID 256
#define NTILES (NPAD / 128)  // 782
#define SCAN_FLAG 0x40000000

// ---------------- scratch (static __device__ arrays; device-code refs only) -
__device__ int   g_cnt[NN];
__device__ int   g_rowptr[NN + 1];
__device__ int   g_wp[NN];
__device__ __align__(8) int2 g_colw[NE];      // {src, __float_as_int(dinv[src])}
__device__ float g_dinv[NN];
__device__ int   g_bsum[128];
__device__ __align__(16) __half g_xh [(size_t)NN   * D_IN];   // x fp16
__device__ __align__(16) __half g_xa [(size_t)NPAD * D_IN];   // A@x fp16
__device__ __align__(16) __half g_h1 [(size_t)NPAD * D_HID];  // relu(xa@W1+b1)
__device__ __align__(16) __half g_y  [(size_t)NPAD * D_IN];   // h1@W2
__device__ __align__(16) __half g_w1h[D_IN * D_HID];
__device__ __align__(16) __half g_w2h[D_HID * D_IN];

// ---------------- fused convert + zero ---------------------------------------
__global__ void k_prep(const float* __restrict__ x,
                       const float* __restrict__ W1,
                       const float* __restrict__ W2) {
    int i = blockIdx.x * 256 + threadIdx.x;
    if (i < NN * 32) {
        float4 v = ((const float4*)x)[i];
        __half2 h0 = __floats2half2_rn(v.x, v.y);
        __half2 h1 = __floats2half2_rn(v.z, v.w);
        ((uint2*)g_xh)[i] = make_uint2(*(uint32_t*)&h0, *(uint32_t*)&h1);
    }
    if (i < NN) g_cnt[i] = 0;
    if (i < 128) g_bsum[i] = 0;               // clear scan flags (graph replay!)
    if (i < (D_IN * D_HID) / 4) {
        float4 a = ((const float4*)W1)[i];
        float4 b = ((const float4*)W2)[i];
        __half2 a0 = __floats2half2_rn(a.x, a.y), a1 = __floats2half2_rn(a.z, a.w);
        __half2 b0 = __floats2half2_rn(b.x, b.y), b1 = __floats2half2_rn(b.z, b.w);
        ((uint2*)g_w1h)[i] = make_uint2(*(uint32_t*)&a0, *(uint32_t*)&a1);
        ((uint2*)g_w2h)[i] = make_uint2(*(uint32_t*)&b0, *(uint32_t*)&b1);
    }
}
__global__ void k_hist(const int* __restrict__ ei) {
    int e = blockIdx.x * blockDim.x + threadIdx.x;
    if (e < NE) atomicAdd(&g_cnt[ei[NE + e]], 1);
}

// ---------------- single-pass scan + finalize (98 blocks, all resident) -----
__global__ void k_scanfuse() {
    __shared__ int sh[1024];
    __shared__ int s_base;
    int bid = blockIdx.x, tid = threadIdx.x;
    int i = bid * 1024 + tid;
    int v = (i < NN) ? g_cnt[i] : 0;
    sh[tid] = v;
    if (tid == 0) s_base = 0;
    __syncthreads();
    for (int off = 1; off < 1024; off <<= 1) {
        int t = (tid >= off) ? sh[tid - off] : 0;
        __syncthreads();
        sh[tid] += t;
        __syncthreads();
    }
    int incl = sh[tid];
    if (tid == 1023) atomicExch(&g_bsum[bid], sh[1023] | SCAN_FLAG);  // publish
    // decoupled wait: thread t < bid spins on predecessor t's aggregate
    if (tid < bid) {
        int p;
        do { p = atomicAdd(&g_bsum[tid], 0); } while (!(p & SCAN_FLAG));
        atomicAdd(&s_base, p & ~SCAN_FLAG);
    }
    __syncthreads();
    if (i < NN) {
        int rp = (incl - v) + s_base;          // global exclusive prefix
        g_rowptr[i] = rp;
        g_wp[i] = rp;
        g_dinv[i] = rsqrtf((float)(v + 1));
    }
    if (i == 0) g_rowptr[NN] = NE;
}
__global__ void k_fill(const int* __restrict__ ei) {
    int e = blockIdx.x * blockDim.x + threadIdx.x;
    if (e < NE) {
        int s = ei[e];
        int d = ei[NE + e];
        int pos = atomicAdd(&g_wp[d], 1);
        g_colw[pos] = make_int2(s, __float_as_int(g_dinv[s]));
    }
}

// ---------------- aggregation: coalesced edge records, MLP-4 gather --------
__device__ __forceinline__ void fma_row(float4& acc, uint2 raw, float w) {
    float2 f0 = __half22float2(*(__half2*)&raw.x);
    float2 f1 = __half22float2(*(__half2*)&raw.y);
    acc.x += f0.x * w; acc.y += f0.y * w;
    acc.z += f1.x * w; acc.w += f1.y * w;
}

__device__ __forceinline__ float4 agg_row_h(const __half* __restrict__ X,
                                            int node, int lane) {
    const uint2* Xv = (const uint2*)X;
    float4 acc = make_float4(0.f, 0.f, 0.f, 0.f);
    int r0 = g_rowptr[node], r1 = g_rowptr[node + 1];
    float di = g_dinv[node];

    for (int base = r0; base < r1; base += 32) {
        int n = r1 - base; if (n > 32) n = 32;
        int2 cw = g_colw[base + (lane < n ? lane : 0)];   // coalesced
        int t = 0;
#pragma unroll 1
        for (; t + 4 <= n; t += 4) {                      // MLP=4: 4 indep LDGs
            int   s0 = __shfl_sync(0xffffffffu, cw.x, t);
            int   s1 = __shfl_sync(0xffffffffu, cw.x, t + 1);
            int   s2 = __shfl_sync(0xffffffffu, cw.x, t + 2);
            int   s3 = __shfl_sync(0xffffffffu, cw.x, t + 3);
            float w0 = __int_as_float(__shfl_sync(0xffffffffu, cw.y, t));
            float w1 = __int_as_float(__shfl_sync(0xffffffffu, cw.y, t + 1));
            float w2 = __int_as_float(__shfl_sync(0xffffffffu, cw.y, t + 2));
            float w3 = __int_as_float(__shfl_sync(0xffffffffu, cw.y, t + 3));
            uint2 q0 = Xv[(size_t)s0 * 32 + lane];
            uint2 q1 = Xv[(size_t)s1 * 32 + lane];
            uint2 q2 = Xv[(size_t)s2 * 32 + lane];
            uint2 q3 = Xv[(size_t)s3 * 32 + lane];
            fma_row(acc, q0, w0);
            fma_row(acc, q1, w1);
            fma_row(acc, q2, w2);
            fma_row(acc, q3, w3);
        }
#pragma unroll 1
        for (; t < n; t++) {
            int   s = __shfl_sync(0xffffffffu, cw.x, t);
            float w = __int_as_float(__shfl_sync(0xffffffffu, cw.y, t));
            fma_row(acc, Xv[(size_t)s * 32 + lane], w);
        }
    }
    uint2 raw = Xv[(size_t)node * 32 + lane];             // self-loop
    float2 f0 = __half22float2(*(__half2*)&raw.x);
    float2 f1 = __half22float2(*(__half2*)&raw.y);
    acc.x = (acc.x + f0.x * di) * di;
    acc.y = (acc.y + f0.y * di) * di;
    acc.z = (acc.z + f1.x * di) * di;
    acc.w = (acc.w + f1.y * di) * di;
    return acc;
}

__global__ void k_agg1() {
    int gw   = (blockIdx.x * blockDim.x + threadIdx.x) >> 5;
    int lane = threadIdx.x & 31;
    if (gw >= NN) return;
    float4 a = agg_row_h(g_xh, gw, lane);
    __half2 h0 = __floats2half2_rn(a.x, a.y);
    __half2 h1 = __floats2half2_rn(a.z, a.w);
    ((uint2*)g_xa)[(size_t)gw * 32 + lane] =
        make_uint2(*(uint32_t*)&h0, *(uint32_t*)&h1);
}

__global__ void k_agg2(float* __restrict__ out,
                       const float* __restrict__ bias,
                       const float* __restrict__ gamma,
                       const float* __restrict__ beta) {
    int gw   = (blockIdx.x * blockDim.x + threadIdx.x) >> 5;
    int lane = threadIdx.x & 31;
    if (gw >= NN) return;
    float4 acc = agg_row_h(g_y, gw, lane);

    float4 bb = ((const float4*)bias)[lane];
    acc.x += bb.x; acc.y += bb.y; acc.z += bb.z; acc.w += bb.w;

    float s = acc.x + acc.y + acc.z + acc.w;
#pragma unroll
    for (int o = 16; o; o >>= 1) s += __shfl_xor_sync(0xffffffffu, s, o);
    float mu = s * (1.f / 128.f);

    float d0 = acc.x - mu, d1 = acc.y - mu, d2 = acc.z - mu, d3 = acc.w - mu;
    float ss = d0 * d0 + d1 * d1 + d2 * d2 + d3 * d3;
#pragma unroll
    for (int o = 16; o; o >>= 1) ss += __shfl_xor_sync(0xffffffffu, ss, o);
    float rs = rsqrtf(ss * (1.f / 128.f) + 1e-5f);

    float4 g  = ((const float4*)gamma)[lane];
    float4 be = ((const float4*)beta)[lane];
    float4 o4;
    o4.x = d0 * rs * g.x + be.x;
    o4.y = d1 * rs * g.y + be.y;
    o4.z = d2 * rs * g.z + be.z;
    o4.w = d3 * rs * g.w + be.w;
    ((float4*)out)[(size_t)gw * 32 + lane] = o4;
}

// ---------------- fp16 mma.sync GEMM with ldmatrix (round-10 staging) -------
__device__ __forceinline__ uint32_t smem_u32(const void* p) {
    uint32_t a;
    asm("{ .reg .u64 t; cvta.to.shared.u64 t, %1; cvt.u32.u64 %0, t; }"
        : "=r"(a) : "l"(p));
    return a;
}
__device__ __forceinline__ void ldsm_x4(uint32_t* r, uint32_t addr) {
    asm volatile("ldmatrix.sync.aligned.m8n8.x4.shared.b16 {%0,%1,%2,%3}, [%4];"
        : "=r"(r[0]), "=r"(r[1]), "=r"(r[2]), "=r"(r[3]) : "r"(addr));
}
__device__ __forceinline__ void ldsm_x2t(uint32_t* r, uint32_t addr) {
    asm volatile("ldmatrix.sync.aligned.m8n8.x2.trans.shared.b16 {%0,%1}, [%2];"
        : "=r"(r[0]), "=r"(r[1]) : "r"(addr));
}
__device__ __forceinline__ void mma_f16(float* c, const uint32_t* a, const uint32_t* b) {
    asm volatile(
        "mma.sync.aligned.m16n8k16.row.col.f32.f16.f16.f32 "
        "{%0,%1,%2,%3}, {%4,%5,%6,%7}, {%8,%9}, {%0,%1,%2,%3};"
        : "+f"(c[0]), "+f"(c[1]), "+f"(c[2]), "+f"(c[3])
        : "r"(a[0]), "r"(a[1]), "r"(a[2]), "r"(a[3]), "r"(b[0]), "r"(b[1]));
}

template <int K, int NT, bool BIAS_RELU>
__device__ __forceinline__ void mma_body_h(const __half* __restrict__ A,
                                           const __half* __restrict__ B,
                                           const float* __restrict__ bias,
                                           __half* __restrict__ C) {
    __shared__ __align__(16) char Asm[2][8192];
    __shared__ __align__(16) char Bsm[2][8192];

    int tid = threadIdx.x, wid = tid >> 5, lane = tid & 31;
    int wm = wid >> 2, wn = wid & 3;          // 2x4 warps, 64x32 warp tile
    int rowBase = blockIdx.y * 128;
    int nBase   = blockIdx.x * 128;

    const __half* Ab = A + (size_t)rowBase * K;
    const __half* Bb = B + nBase;

    float acc[4][4][4];
#pragma unroll
    for (int i = 0; i < 4; i++)
#pragma unroll
        for (int j = 0; j < 4; j++)
#pragma unroll
            for (int q = 0; q < 4; q++) acc[i][j][q] = 0.f;

    uint4 sa[2], sb[2];
    auto ldStage = [&](int ch) {
#pragma unroll
        for (int it = 0; it < 2; it++) {
            int u = tid + it * 256;
            sa[it] = *(const uint4*)(Ab + (size_t)(u >> 2) * K + ch * 32 + (u & 3) * 8);
            sb[it] = *(const uint4*)(Bb + (size_t)(ch * 32 + (u >> 4)) * NT + (u & 15) * 8);
        }
    };
    auto stStage = [&](int buf) {
#pragma unroll
        for (int it = 0; it < 2; it++) {
            int u = tid + it * 256;
            int r = u >> 2, c16 = u & 3;
            *(uint4*)(Asm[buf] + r * 64 + ((c16 ^ ((r >> 1) & 3)) << 4)) = sa[it];
            int k = u >> 4, d16 = u & 15;
            *(uint4*)(Bsm[buf] + k * 256 + ((d16 ^ (k & 7)) << 4)) = sb[it];
        }
    };

    const int nch = K >> 5;
    ldStage(0);
    stStage(0);
    __syncthreads();

    int aG  = lane >> 3;
    int aRl = (aG & 1) * 8 + (lane & 7);
    int aCo = aG >> 1;
    int bK  = lane & 15;

#pragma unroll 1
    for (int ch = 0; ch < nch; ch++) {
        int buf = ch & 1;
        if (ch + 1 < nch) ldStage(ch + 1);

        uint32_t aBase = smem_u32(Asm[buf]);
        uint32_t bBase = smem_u32(Bsm[buf]);
#pragma unroll
        for (int ks = 0; ks < 2; ks++) {
            uint32_t af[4][4], bf[4][2];
#pragma unroll
            for (int i = 0; i < 4; i++) {
                int r   = (wm * 4 + i) * 16 + aRl;
                int c16 = ks * 2 + aCo;
                ldsm_x4(af[i], aBase + r * 64 + ((c16 ^ ((r >> 1) & 3)) << 4));
            }
#pragma unroll
            for (int j = 0; j < 4; j++) {
                int ntile = wn * 4 + j;
                int k = ks * 16 + bK;
                ldsm_x2t(bf[j], bBase + k * 256 + ((ntile ^ (k & 7)) << 4));
            }
#pragma unroll
            for (int i = 0; i < 4; i++)
#pragma unroll
                for (int j = 0; j < 4; j++)
                    mma_f16(acc[i][j], af[i], bf[j]);
        }

        if (ch + 1 < nch) stStage(buf ^ 1);
        __syncthreads();
    }

    // epilogue (fp16 out)
    int crow = rowBase + wm * 64 + (lane >> 2);
    int ccol = nBase + wn * 32 + (lane & 3) * 2;
#pragma unroll
    for (int i = 0; i < 4; i++) {
#pragma unroll
        for (int j = 0; j < 4; j++) {
            int r0 = crow + i * 16, c0 = ccol + j * 8;
            float2 v0 = make_float2(acc[i][j][0], acc[i][j][1]);
            float2 v1 = make_float2(acc[i][j][2], acc[i][j][3]);
            if (BIAS_RELU) {
                float bx = bias[c0], by = bias[c0 + 1];
                v0.x = fmaxf(v0.x + bx, 0.f); v0.y = fmaxf(v0.y + by, 0.f);
                v1.x = fmaxf(v1.x + bx, 0.f); v1.y = fmaxf(v1.y + by, 0.f);
            }
            *(__half2*)&C[(size_t)r0 * NT + c0]       = __floats2half2_rn(v0.x, v0.y);
            *(__half2*)&C[(size_t)(r0 + 8) * NT + c0] = __floats2half2_rn(v1.x, v1.y);
        }
    }
}

__global__ __launch_bounds__(256)
void k_mma1(const float* __restrict__ b1) {
    mma_body_h<D_IN, D_HID, true>(g_xa, g_w1h, b1, g_h1);
}
__global__ __launch_bounds__(256)
void k_mma2() {
    mma_body_h<D_HID, D_IN, false>(g_h1, g_w2h, nullptr, g_y);
}

// ---------------- launch (kernel launches ONLY) -----------------------------
extern "C" void kernel_launch(void* const* d_in, const int* in_sizes, int n_in,
                              void* d_out, int out_size) {
    const float* x     = (const float*)d_in[0];
    const int*   ei    = (const int*)d_in[1];      // int32 edge_index [2, NE]
    const float* W1    = (const float*)d_in[2];
    const float* b1    = (const float*)d_in[3];
    const float* W2    = (const float*)d_in[4];
    const float* b2    = (const float*)d_in[5];
    const float* gamma = (const float*)d_in[6];
    const float* beta  = (const float*)d_in[7];
    float* out = (float*)d_out;

    k_prep    <<<(NN * 32 + 255) / 256, 256>>>(x, W1, W2);
    k_hist    <<<(NE + 255) / 256, 256>>>(ei);
    k_scanfuse<<<98, 1024>>>();
    k_fill    <<<(NE + 255) / 256, 256>>>(ei);

    // xa = A @ x  (fp16 gather, MLP-4, fp32 accum, fp16 out)
    k_agg1<<<(NN * 32) / 256, 256>>>();

    // h1 = relu(xa @ W1 + b1)   (fp16 mma + ldmatrix)
    dim3 g1(D_HID / 128, NTILES);
    k_mma1<<<g1, 256>>>(b1);

    // y = h1 @ W2
    dim3 g2(D_IN / 128, NTILES);
    k_mma2<<<g2, 256>>>();

    // out = LayerNorm(A @ y + b2)
    k_agg2<<<(NN * 32) / 256, 256>>>(out, b2, gamma, beta);
}

// round 14
// speedup vs baseline: 1.1608x; 1.1225x over previous
#include <cuda_runtime.h>
#include <cuda_fp16.h>
#include <cstdint>

#define NN   100000
#define NE   1600000
#define NPAD 100096          // 782 * 128
#define D_IN  128
#define D_HID 256
#define NTILES (NPAD / 128)  // 782
#define SCAN_FLAG 0x40000000

// ---------------- scratch (static __device__ arrays; device-code refs only) -
__device__ int   g_cnt[NN];
__device__ int   g_rowptr[NN + 1];
__device__ int   g_wp[NN];
__device__ int   g_col[NE];                    // src index only (rows pre-scaled)
__device__ float g_dinv[NN];
__device__ int   g_bsum[128];
__device__ __align__(16) __half g_xh [(size_t)NN   * D_IN];   // dinv*x fp16
__device__ __align__(16) __half g_xa [(size_t)NPAD * D_IN];   // A@x fp16
__device__ __align__(16) __half g_h1 [(size_t)NPAD * D_HID];  // relu(xa@W1+b1)
__device__ __align__(16) __half g_y  [(size_t)NPAD * D_IN];   // dinv*(h1@W2) fp16
__device__ __align__(16) __half g_w1h[D_IN * D_HID];
__device__ __align__(16) __half g_w2h[D_HID * D_IN];

// ---------------- prep: zero counters, convert weights ----------------------
__global__ void k_prep(const float* __restrict__ W1,
                       const float* __restrict__ W2) {
    int i = blockIdx.x * 256 + threadIdx.x;
    if (i < NN) g_cnt[i] = 0;
    if (i < 128) g_bsum[i] = 0;               // clear scan flags (graph replay!)
    if (i < (D_IN * D_HID) / 4) {
        float4 a = ((const float4*)W1)[i];
        float4 b = ((const float4*)W2)[i];
        __half2 a0 = __floats2half2_rn(a.x, a.y), a1 = __floats2half2_rn(a.z, a.w);
        __half2 b0 = __floats2half2_rn(b.x, b.y), b1 = __floats2half2_rn(b.z, b.w);
        ((uint2*)g_w1h)[i] = make_uint2(*(uint32_t*)&a0, *(uint32_t*)&a1);
        ((uint2*)g_w2h)[i] = make_uint2(*(uint32_t*)&b0, *(uint32_t*)&b1);
    }
}
__global__ void k_hist(const int* __restrict__ ei) {
    int e = blockIdx.x * blockDim.x + threadIdx.x;
    if (e < NE) atomicAdd(&g_cnt[ei[NE + e]], 1);
}

// ---------------- single-pass scan + finalize (98 blocks, all resident) -----
__global__ void k_scanfuse() {
    __shared__ int sh[1024];
    __shared__ int s_base;
    int bid = blockIdx.x, tid = threadIdx.x;
    int i = bid * 1024 + tid;
    int v = (i < NN) ? g_cnt[i] : 0;
    sh[tid] = v;
    if (tid == 0) s_base = 0;
    __syncthreads();
    for (int off = 1; off < 1024; off <<= 1) {
        int t = (tid >= off) ? sh[tid - off] : 0;
        __syncthreads();
        sh[tid] += t;
        __syncthreads();
    }
    int incl = sh[tid];
    if (tid == 1023) atomicExch(&g_bsum[bid], sh[1023] | SCAN_FLAG);  // publish
    if (tid < bid) {                           // decoupled wait on predecessors
        int p;
        do { p = atomicAdd(&g_bsum[tid], 0); } while (!(p & SCAN_FLAG));
        atomicAdd(&s_base, p & ~SCAN_FLAG);
    }
    __syncthreads();
    if (i < NN) {
        int rp = (incl - v) + s_base;          // global exclusive prefix
        g_rowptr[i] = rp;
        g_wp[i] = rp;
        g_dinv[i] = rsqrtf((float)(v + 1));
    }
    if (i == 0) g_rowptr[NN] = NE;
}

// ---------------- fused CSR fill + x pre-scale+convert ----------------------
// grid covers NN*32 float4s (3.2M) >= NE (1.6M)
__global__ void k_fillscale(const int* __restrict__ ei,
                            const float* __restrict__ x) {
    int gid = blockIdx.x * 256 + threadIdx.x;
    if (gid < NE) {
        int s = ei[gid];
        int d = ei[NE + gid];
        int pos = atomicAdd(&g_wp[d], 1);
        g_col[pos] = s;
    }
    if (gid < NN * 32) {
        float4 v = ((const float4*)x)[gid];
        float dv = g_dinv[gid >> 5];
        __half2 h0 = __floats2half2_rn(v.x * dv, v.y * dv);
        __half2 h1 = __floats2half2_rn(v.z * dv, v.w * dv);
        ((uint2*)g_xh)[gid] = make_uint2(*(uint32_t*)&h0, *(uint32_t*)&h1);
    }
}

// ---------------- aggregation: unweighted row sum (rows pre-scaled) --------
__device__ __forceinline__ void add_row(float4& acc, uint2 raw) {
    float2 f0 = __half22float2(*(__half2*)&raw.x);
    float2 f1 = __half22float2(*(__half2*)&raw.y);
    acc.x += f0.x; acc.y += f0.y; acc.z += f1.x; acc.w += f1.y;
}

__device__ __forceinline__ float4 agg_row_h(const __half* __restrict__ X,
                                            int node, int lane) {
    const uint2* Xv = (const uint2*)X;
    float4 acc = make_float4(0.f, 0.f, 0.f, 0.f);
    int r0 = g_rowptr[node], r1 = g_rowptr[node + 1];

    for (int base = r0; base < r1; base += 32) {
        int n = r1 - base; if (n > 32) n = 32;
        int c = g_col[base + (lane < n ? lane : 0)];      // coalesced
        int t = 0;
#pragma unroll 1
        for (; t + 4 <= n; t += 4) {                      // MLP=4
            int s0 = __shfl_sync(0xffffffffu, c, t);
            int s1 = __shfl_sync(0xffffffffu, c, t + 1);
            int s2 = __shfl_sync(0xffffffffu, c, t + 2);
            int s3 = __shfl_sync(0xffffffffu, c, t + 3);
            uint2 q0 = Xv[(size_t)s0 * 32 + lane];
            uint2 q1 = Xv[(size_t)s1 * 32 + lane];
            uint2 q2 = Xv[(size_t)s2 * 32 + lane];
            uint2 q3 = Xv[(size_t)s3 * 32 + lane];
            add_row(acc, q0);
            add_row(acc, q1);
            add_row(acc, q2);
            add_row(acc, q3);
        }
#pragma unroll 1
        for (; t < n; t++) {
            int s = __shfl_sync(0xffffffffu, c, t);
            add_row(acc, Xv[(size_t)s * 32 + lane]);
        }
    }
    add_row(acc, Xv[(size_t)node * 32 + lane]);           // self-loop (pre-scaled)
    float di = g_dinv[node];
    acc.x *= di; acc.y *= di; acc.z *= di; acc.w *= di;
    return acc;
}

__global__ void k_agg1() {
    int gw   = (blockIdx.x * blockDim.x + threadIdx.x) >> 5;
    int lane = threadIdx.x & 31;
    if (gw >= NN) return;
    float4 a = agg_row_h(g_xh, gw, lane);
    __half2 h0 = __floats2half2_rn(a.x, a.y);
    __half2 h1 = __floats2half2_rn(a.z, a.w);
    ((uint2*)g_xa)[(size_t)gw * 32 + lane] =
        make_uint2(*(uint32_t*)&h0, *(uint32_t*)&h1);
}

__global__ void k_agg2(float* __restrict__ out,
                       const float* __restrict__ bias,
                       const float* __restrict__ gamma,
                       const float* __restrict__ beta) {
    int gw   = (blockIdx.x * blockDim.x + threadIdx.x) >> 5;
    int lane = threadIdx.x & 31;
    if (gw >= NN) return;
    float4 acc = agg_row_h(g_y, gw, lane);

    float4 bb = ((const float4*)bias)[lane];
    acc.x += bb.x; acc.y += bb.y; acc.z += bb.z; acc.w += bb.w;

    float s = acc.x + acc.y + acc.z + acc.w;
#pragma unroll
    for (int o = 16; o; o >>= 1) s += __shfl_xor_sync(0xffffffffu, s, o);
    float mu = s * (1.f / 128.f);

    float d0 = acc.x - mu, d1 = acc.y - mu, d2 = acc.z - mu, d3 = acc.w - mu;
    float ss = d0 * d0 + d1 * d1 + d2 * d2 + d3 * d3;
#pragma unroll
    for (int o = 16; o; o >>= 1) ss += __shfl_xor_sync(0xffffffffu, ss, o);
    float rs = rsqrtf(ss * (1.f / 128.f) + 1e-5f);

    float4 g  = ((const float4*)gamma)[lane];
    float4 be = ((const float4*)beta)[lane];
    float4 o4;
    o4.x = d0 * rs * g.x + be.x;
    o4.y = d1 * rs * g.y + be.y;
    o4.z = d2 * rs * g.z + be.z;
    o4.w = d3 * rs * g.w + be.w;
    ((float4*)out)[(size_t)gw * 32 + lane] = o4;
}

// ---------------- fp16 mma.sync GEMM with ldmatrix --------------------------
__device__ __forceinline__ uint32_t smem_u32(const void* p) {
    uint32_t a;
    asm("{ .reg .u64 t; cvta.to.shared.u64 t, %1; cvt.u32.u64 %0, t; }"
        : "=r"(a) : "l"(p));
    return a;
}
__device__ __forceinline__ void ldsm_x4(uint32_t* r, uint32_t addr) {
    asm volatile("ldmatrix.sync.aligned.m8n8.x4.shared.b16 {%0,%1,%2,%3}, [%4];"
        : "=r"(r[0]), "=r"(r[1]), "=r"(r[2]), "=r"(r[3]) : "r"(addr));
}
__device__ __forceinline__ void ldsm_x2t(uint32_t* r, uint32_t addr) {
    asm volatile("ldmatrix.sync.aligned.m8n8.x2.trans.shared.b16 {%0,%1}, [%2];"
        : "=r"(r[0]), "=r"(r[1]) : "r"(addr));
}
__device__ __forceinline__ void mma_f16(float* c, const uint32_t* a, const uint32_t* b) {
    asm volatile(
        "mma.sync.aligned.m16n8k16.row.col.f32.f16.f16.f32 "
        "{%0,%1,%2,%3}, {%4,%5,%6,%7}, {%8,%9}, {%0,%1,%2,%3};"
        : "+f"(c[0]), "+f"(c[1]), "+f"(c[2]), "+f"(c[3])
        : "r"(a[0]), "r"(a[1]), "r"(a[2]), "r"(a[3]), "r"(b[0]), "r"(b[1]));
}

// SCALE_DINV: epilogue multiplies row r by g_dinv[r] (pre-scaling for agg2)
template <int K, int NT, bool BIAS_RELU, bool SCALE_DINV>
__device__ __forceinline__ void mma_body_h(const __half* __restrict__ A,
                                           const __half* __restrict__ B,
                                           const float* __restrict__ bias,
                                           __half* __restrict__ C) {
    __shared__ __align__(16) char Asm[2][8192];
    __shared__ __align__(16) char Bsm[2][8192];

    int tid = threadIdx.x, wid = tid >> 5, lane = tid & 31;
    int wm = wid >> 2, wn = wid & 3;          // 2x4 warps, 64x32 warp tile
    int rowBase = blockIdx.y * 128;
    int nBase   = blockIdx.x * 128;

    const __half* Ab = A + (size_t)rowBase * K;
    const __half* Bb = B + nBase;

    float acc[4][4][4];
#pragma unroll
    for (int i = 0; i < 4; i++)
#pragma unroll
        for (int j = 0; j < 4; j++)
#pragma unroll
            for (int q = 0; q < 4; q++) acc[i][j][q] = 0.f;

    uint4 sa[2], sb[2];
    auto ldStage = [&](int ch) {
#pragma unroll
        for (int it = 0; it < 2; it++) {
            int u = tid + it * 256;
            sa[it] = *(const uint4*)(Ab + (size_t)(u >> 2) * K + ch * 32 + (u & 3) * 8);
            sb[it] = *(const uint4*)(Bb + (size_t)(ch * 32 + (u >> 4)) * NT + (u & 15) * 8);
        }
    };
    auto stStage = [&](int buf) {
#pragma unroll
        for (int it = 0; it < 2; it++) {
            int u = tid + it * 256;
            int r = u >> 2, c16 = u & 3;
            *(uint4*)(Asm[buf] + r * 64 + ((c16 ^ ((r >> 1) & 3)) << 4)) = sa[it];
            int k = u >> 4, d16 = u & 15;
            *(uint4*)(Bsm[buf] + k * 256 + ((d16 ^ (k & 7)) << 4)) = sb[it];
        }
    };

    const int nch = K >> 5;
    ldStage(0);
    stStage(0);
    __syncthreads();

    int aG  = lane >> 3;
    int aRl = (aG & 1) * 8 + (lane & 7);
    int aCo = aG >> 1;
    int bK  = lane & 15;

#pragma unroll 1
    for (int ch = 0; ch < nch; ch++) {
        int buf = ch & 1;
        if (ch + 1 < nch) ldStage(ch + 1);

        uint32_t aBase = smem_u32(Asm[buf]);
        uint32_t bBase = smem_u32(Bsm[buf]);
#pragma unroll
        for (int ks = 0; ks < 2; ks++) {
            uint32_t af[4][4], bf[4][2];
#pragma unroll
            for (int i = 0; i < 4; i++) {
                int r   = (wm * 4 + i) * 16 + aRl;
                int c16 = ks * 2 + aCo;
                ldsm_x4(af[i], aBase + r * 64 + ((c16 ^ ((r >> 1) & 3)) << 4));
            }
#pragma unroll
            for (int j = 0; j < 4; j++) {
                int ntile = wn * 4 + j;
                int k = ks * 16 + bK;
                ldsm_x2t(bf[j], bBase + k * 256 + ((ntile ^ (k & 7)) << 4));
            }
#pragma unroll
            for (int i = 0; i < 4; i++)
#pragma unroll
                for (int j = 0; j < 4; j++)
                    mma_f16(acc[i][j], af[i], bf[j]);
        }

        if (ch + 1 < nch) stStage(buf ^ 1);
        __syncthreads();
    }

    // epilogue (fp16 out, optional per-row dinv pre-scale)
    int crow = rowBase + wm * 64 + (lane >> 2);
    int ccol = nBase + wn * 32 + (lane & 3) * 2;
#pragma unroll
    for (int i = 0; i < 4; i++) {
        int r0 = crow + i * 16;
        float dv0 = 1.f, dv1 = 1.f;
        if (SCALE_DINV) {
            dv0 = (r0 < NN)     ? g_dinv[r0]     : 0.f;
            dv1 = (r0 + 8 < NN) ? g_dinv[r0 + 8] : 0.f;
        }
#pragma unroll
        for (int j = 0; j < 4; j++) {
            int c0 = ccol + j * 8;
            float2 v0 = make_float2(acc[i][j][0], acc[i][j][1]);
            float2 v1 = make_float2(acc[i][j][2], acc[i][j][3]);
            if (BIAS_RELU) {
                float bx = bias[c0], by = bias[c0 + 1];
                v0.x = fmaxf(v0.x + bx, 0.f); v0.y = fmaxf(v0.y + by, 0.f);
                v1.x = fmaxf(v1.x + bx, 0.f); v1.y = fmaxf(v1.y + by, 0.f);
            }
            if (SCALE_DINV) {
                v0.x *= dv0; v0.y *= dv0;
                v1.x *= dv1; v1.y *= dv1;
            }
            *(__half2*)&C[(size_t)r0 * NT + c0]       = __floats2half2_rn(v0.x, v0.y);
            *(__half2*)&C[(size_t)(r0 + 8) * NT + c0] = __floats2half2_rn(v1.x, v1.y);
        }
    }
}

__global__ __launch_bounds__(256)
void k_mma1(const float* __restrict__ b1) {
    mma_body_h<D_IN, D_HID, true, false>(g_xa, g_w1h, b1, g_h1);
}
__global__ __launch_bounds__(256)
void k_mma2() {
    mma_body_h<D_HID, D_IN, false, true>(g_h1, g_w2h, nullptr, g_y);
}

// ---------------- launch (kernel launches ONLY) -----------------------------
extern "C" void kernel_launch(void* const* d_in, const int* in_sizes, int n_in,
                              void* d_out, int out_size) {
    const float* x     = (const float*)d_in[0];
    const int*   ei    = (const int*)d_in[1];      // int32 edge_index [2, NE]
    const float* W1    = (const float*)d_in[2];
    const float* b1    = (const float*)d_in[3];
    const float* W2    = (const float*)d_in[4];
    const float* b2    = (const float*)d_in[5];
    const float* gamma = (const float*)d_in[6];
    const float* beta  = (const float*)d_in[7];
    float* out = (float*)d_out;

    k_prep     <<<(NN + 255) / 256, 256>>>(W1, W2);
    k_hist     <<<(NE + 255) / 256, 256>>>(ei);
    k_scanfuse <<<98, 1024>>>();
    k_fillscale<<<(NN * 32 + 255) / 256, 256>>>(ei, x);

    // xa = A @ x  (unweighted fp16 gather of pre-scaled rows)
    k_agg1<<<(NN * 32) / 256, 256>>>();

    // h1 = relu(xa @ W1 + b1)
    dim3 g1(D_HID / 128, NTILES);
    k_mma1<<<g1, 256>>>(b1);

    // y = dinv * (h1 @ W2)   (pre-scaled in epilogue)
    dim3 g2(D_IN / 128, NTILES);
    k_mma2<<<g2, 256>>>();

    // out = LayerNorm(A @ y + b2)
    k_agg2<<<(NN * 32) / 256, 256>>>(out, b2, gamma, beta);
}

// round 15
// speedup vs baseline: 1.2320x; 1.0613x over previous
#include <cuda_runtime.h>
#include <cuda_fp16.h>
#include <cstdint>

#define NN   100000
#define NE   1600000
#define NPAD 100096          // 782 * 128
#define D_IN  128
#define D_HID 256
#define NTILES (NPAD / 128)  // 782
#define SCAN_FLAG 0x40000000

// ---------------- scratch (static __device__ arrays; device-code refs only) -
__device__ int   g_cnt[NN];
__device__ int   g_rowptr[NN + 1];
__device__ int   g_wp[NN];
__device__ int   g_col[NE];                    // src index only (rows pre-scaled)
__device__ float g_dinv[NN];
__device__ int   g_bsum[128];
__device__ __align__(16) __half g_xh [(size_t)NN   * D_IN];   // dinv*x fp16
__device__ __align__(16) __half g_xa [(size_t)NPAD * D_IN];   // A@x fp16
__device__ __align__(16) __half g_y  [(size_t)NPAD * D_IN];   // dinv*(h1@W2) fp16
__device__ __align__(16) __half g_w1h[D_IN * D_HID];
__device__ __align__(16) __half g_w2h[D_HID * D_IN];

// ---------------- prep: zero counters, convert weights ----------------------
__global__ void k_prep(const float* __restrict__ W1,
                       const float* __restrict__ W2) {
    int i = blockIdx.x * 256 + threadIdx.x;
    if (i < NN) g_cnt[i] = 0;
    if (i < 128) g_bsum[i] = 0;               // clear scan flags (graph replay!)
    if (i < (D_IN * D_HID) / 4) {
        float4 a = ((const float4*)W1)[i];
        float4 b = ((const float4*)W2)[i];
        __half2 a0 = __floats2half2_rn(a.x, a.y), a1 = __floats2half2_rn(a.z, a.w);
        __half2 b0 = __floats2half2_rn(b.x, b.y), b1 = __floats2half2_rn(b.z, b.w);
        ((uint2*)g_w1h)[i] = make_uint2(*(uint32_t*)&a0, *(uint32_t*)&a1);
        ((uint2*)g_w2h)[i] = make_uint2(*(uint32_t*)&b0, *(uint32_t*)&b1);
    }
}
__global__ void k_hist(const int* __restrict__ ei) {
    int e = blockIdx.x * blockDim.x + threadIdx.x;
    if (e < NE) atomicAdd(&g_cnt[ei[NE + e]], 1);
}

// ---------------- single-pass scan + finalize (98 blocks, all resident) -----
__global__ void k_scanfuse() {
    __shared__ int sh[1024];
    __shared__ int s_base;
    int bid = blockIdx.x, tid = threadIdx.x;
    int i = bid * 1024 + tid;
    int v = (i < NN) ? g_cnt[i] : 0;
    sh[tid] = v;
    if (tid == 0) s_base = 0;
    __syncthreads();
    for (int off = 1; off < 1024; off <<= 1) {
        int t = (tid >= off) ? sh[tid - off] : 0;
        __syncthreads();
        sh[tid] += t;
        __syncthreads();
    }
    int incl = sh[tid];
    if (tid == 1023) atomicExch(&g_bsum[bid], sh[1023] | SCAN_FLAG);  // publish
    if (tid < bid) {                           // decoupled wait on predecessors
        int p;
        do { p = atomicAdd(&g_bsum[tid], 0); } while (!(p & SCAN_FLAG));
        atomicAdd(&s_base, p & ~SCAN_FLAG);
    }
    __syncthreads();
    if (i < NN) {
        int rp = (incl - v) + s_base;          // global exclusive prefix
        g_rowptr[i] = rp;
        g_wp[i] = rp;
        g_dinv[i] = rsqrtf((float)(v + 1));
    }
    if (i == 0) g_rowptr[NN] = NE;
}

// ---------------- fused CSR fill + x pre-scale+convert ----------------------
__global__ void k_fillscale(const int* __restrict__ ei,
                            const float* __restrict__ x) {
    int gid = blockIdx.x * 256 + threadIdx.x;
    if (gid < NE) {
        int s = ei[gid];
        int d = ei[NE + gid];
        int pos = atomicAdd(&g_wp[d], 1);
        g_col[pos] = s;
    }
    if (gid < NN * 32) {
        float4 v = ((const float4*)x)[gid];
        float dv = g_dinv[gid >> 5];
        __half2 h0 = __floats2half2_rn(v.x * dv, v.y * dv);
        __half2 h1 = __floats2half2_rn(v.z * dv, v.w * dv);
        ((uint2*)g_xh)[gid] = make_uint2(*(uint32_t*)&h0, *(uint32_t*)&h1);
    }
}

// ---------------- aggregation: unweighted row sum (rows pre-scaled) --------
__device__ __forceinline__ void add_row(float4& acc, uint2 raw) {
    float2 f0 = __half22float2(*(__half2*)&raw.x);
    float2 f1 = __half22float2(*(__half2*)&raw.y);
    acc.x += f0.x; acc.y += f0.y; acc.z += f1.x; acc.w += f1.y;
}

__device__ __forceinline__ float4 agg_row_h(const __half* __restrict__ X,
                                            int node, int lane) {
    const uint2* Xv = (const uint2*)X;
    float4 acc = make_float4(0.f, 0.f, 0.f, 0.f);
    int r0 = g_rowptr[node], r1 = g_rowptr[node + 1];

    for (int base = r0; base < r1; base += 32) {
        int n = r1 - base; if (n > 32) n = 32;
        int c = g_col[base + (lane < n ? lane : 0)];      // coalesced
        int t = 0;
#pragma unroll 1
        for (; t + 4 <= n; t += 4) {                      // MLP=4
            int s0 = __shfl_sync(0xffffffffu, c, t);
            int s1 = __shfl_sync(0xffffffffu, c, t + 1);
            int s2 = __shfl_sync(0xffffffffu, c, t + 2);
            int s3 = __shfl_sync(0xffffffffu, c, t + 3);
            uint2 q0 = Xv[(size_t)s0 * 32 + lane];
            uint2 q1 = Xv[(size_t)s1 * 32 + lane];
            uint2 q2 = Xv[(size_t)s2 * 32 + lane];
            uint2 q3 = Xv[(size_t)s3 * 32 + lane];
            add_row(acc, q0);
            add_row(acc, q1);
            add_row(acc, q2);
            add_row(acc, q3);
        }
#pragma unroll 1
        for (; t < n; t++) {
            int s = __shfl_sync(0xffffffffu, c, t);
            add_row(acc, Xv[(size_t)s * 32 + lane]);
        }
    }
    add_row(acc, Xv[(size_t)node * 32 + lane]);           // self-loop (pre-scaled)
    float di = g_dinv[node];
    acc.x *= di; acc.y *= di; acc.z *= di; acc.w *= di;
    return acc;
}

__global__ void k_agg1() {
    int gw   = (blockIdx.x * blockDim.x + threadIdx.x) >> 5;
    int lane = threadIdx.x & 31;
    if (gw >= NN) return;
    float4 a = agg_row_h(g_xh, gw, lane);
    __half2 h0 = __floats2half2_rn(a.x, a.y);
    __half2 h1 = __floats2half2_rn(a.z, a.w);
    ((uint2*)g_xa)[(size_t)gw * 32 + lane] =
        make_uint2(*(uint32_t*)&h0, *(uint32_t*)&h1);
}

__global__ void k_agg2(float* __restrict__ out,
                       const float* __restrict__ bias,
                       const float* __restrict__ gamma,
                       const float* __restrict__ beta) {
    int gw   = (blockIdx.x * blockDim.x + threadIdx.x) >> 5;
    int lane = threadIdx.x & 31;
    if (gw >= NN) return;
    float4 acc = agg_row_h(g_y, gw, lane);

    float4 bb = ((const float4*)bias)[lane];
    acc.x += bb.x; acc.y += bb.y; acc.z += bb.z; acc.w += bb.w;

    float s = acc.x + acc.y + acc.z + acc.w;
#pragma unroll
    for (int o = 16; o; o >>= 1) s += __shfl_xor_sync(0xffffffffu, s, o);
    float mu = s * (1.f / 128.f);

    float d0 = acc.x - mu, d1 = acc.y - mu, d2 = acc.z - mu, d3 = acc.w - mu;
    float ss = d0 * d0 + d1 * d1 + d2 * d2 + d3 * d3;
#pragma unroll
    for (int o = 16; o; o >>= 1) ss += __shfl_xor_sync(0xffffffffu, ss, o);
    float rs = rsqrtf(ss * (1.f / 128.f) + 1e-5f);

    float4 g  = ((const float4*)gamma)[lane];
    float4 be = ((const float4*)beta)[lane];
    float4 o4;
    o4.x = d0 * rs * g.x + be.x;
    o4.y = d1 * rs * g.y + be.y;
    o4.z = d2 * rs * g.z + be.z;
    o4.w = d3 * rs * g.w + be.w;
    ((float4*)out)[(size_t)gw * 32 + lane] = o4;
}

// ---------------- fused double GEMM: y = dinv*(relu(xa@W1+b1)@W2) ------------
__device__ __forceinline__ uint32_t smem_u32(const void* p) {
    uint32_t a;
    asm("{ .reg .u64 t; cvta.to.shared.u64 t, %1; cvt.u32.u64 %0, t; }"
        : "=r"(a) : "l"(p));
    return a;
}
__device__ __forceinline__ void ldsm_x4(uint32_t* r, uint32_t addr) {
    asm volatile("ldmatrix.sync.aligned.m8n8.x4.shared.b16 {%0,%1,%2,%3}, [%4];"
        : "=r"(r[0]), "=r"(r[1]), "=r"(r[2]), "=r"(r[3]) : "r"(addr));
}
__device__ __forceinline__ void ldsm_x2t(uint32_t* r, uint32_t addr) {
    asm volatile("ldmatrix.sync.aligned.m8n8.x2.trans.shared.b16 {%0,%1}, [%2];"
        : "=r"(r[0]), "=r"(r[1]) : "r"(addr));
}
__device__ __forceinline__ void mma_f16(float* c, const uint32_t* a, const uint32_t* b) {
    asm volatile(
        "mma.sync.aligned.m16n8k16.row.col.f32.f16.f16.f32 "
        "{%0,%1,%2,%3}, {%4,%5,%6,%7}, {%8,%9}, {%0,%1,%2,%3};"
        : "+f"(c[0]), "+f"(c[1]), "+f"(c[2]), "+f"(c[3])
        : "r"(a[0]), "r"(a[1]), "r"(a[2]), "r"(a[3]), "r"(b[0]), "r"(b[1]));
}

// SMEM layout (dynamic, 114688 B):
//   h1s  [0      .. 65536)  : h1 tile 128x256 fp16 as 8 swizzled A-chunks (8KB each)
//   Aall [65536  .. 98304)  : xa tile 128x128 fp16 as 4 swizzled A-chunks
//   Bsm  [98304  .. 114688) : 2 x 8KB B staging (32 k-rows x 128 cols)
__global__ __launch_bounds__(256)
void k_fused(const float* __restrict__ b1) {
    extern __shared__ __align__(16) char sm[];
    char* h1s  = sm;
    char* Aall = sm + 65536;
    char* BsmP[2] = {sm + 98304, sm + 106496};

    int tid = threadIdx.x, wid = tid >> 5, lane = tid & 31;
    int wm = wid >> 2, wn = wid & 3;          // 2x4 warps, 64x32 warp tile
    int rowBase = blockIdx.x * 128;

    // ---- stage full A tile (g_xa) into Aall: 4 chunks, swizzled ----
#pragma unroll
    for (int ch = 0; ch < 4; ch++) {
#pragma unroll
        for (int it = 0; it < 2; it++) {
            int u = tid + it * 256;
            int r = u >> 2, c16 = u & 3;
            uint4 v = *(const uint4*)(g_xa + (size_t)(rowBase + r) * D_IN + ch * 32 + c16 * 8);
            *(uint4*)(Aall + ch * 8192 + r * 64 + ((c16 ^ ((r >> 1) & 3)) << 4)) = v;
        }
    }

    uint4 sb[2];
    auto ldB = [&](const __half* Bb, int NT, int ch) {
#pragma unroll
        for (int it = 0; it < 2; it++) {
            int u = tid + it * 256;
            sb[it] = *(const uint4*)(Bb + (size_t)(ch * 32 + (u >> 4)) * NT + (u & 15) * 8);
        }
    };
    auto stB = [&](int buf) {
#pragma unroll
        for (int it = 0; it < 2; it++) {
            int u = tid + it * 256;
            int k = u >> 4, d16 = u & 15;
            *(uint4*)(BsmP[buf] + k * 256 + ((d16 ^ (k & 7)) << 4)) = sb[it];
        }
    };

    int aG  = lane >> 3;
    int aRl = (aG & 1) * 8 + (lane & 7);
    int aCo = aG >> 1;
    int bK  = lane & 15;

    float acc[4][4][4];
    auto zeroAcc = [&]() {
#pragma unroll
        for (int i = 0; i < 4; i++)
#pragma unroll
            for (int j = 0; j < 4; j++)
#pragma unroll
                for (int q = 0; q < 4; q++) acc[i][j][q] = 0.f;
    };
    auto mmaChunk = [&](const char* aChunk, int buf) {
        uint32_t aBase = smem_u32(aChunk);
        uint32_t bBase = smem_u32(BsmP[buf]);
#pragma unroll
        for (int ks = 0; ks < 2; ks++) {
            uint32_t af[4][4], bf[4][2];
#pragma unroll
            for (int i = 0; i < 4; i++) {
                int r   = (wm * 4 + i) * 16 + aRl;
                int c16 = ks * 2 + aCo;
                ldsm_x4(af[i], aBase + r * 64 + ((c16 ^ ((r >> 1) & 3)) << 4));
            }
#pragma unroll
            for (int j = 0; j < 4; j++) {
                int ntile = wn * 4 + j;
                int k = ks * 16 + bK;
                ldsm_x2t(bf[j], bBase + k * 256 + ((ntile ^ (k & 7)) << 4));
            }
#pragma unroll
            for (int i = 0; i < 4; i++)
#pragma unroll
                for (int j = 0; j < 4; j++)
                    mma_f16(acc[i][j], af[i], bf[j]);
        }
    };

    // ================= phase 1: h1 = relu(xa @ W1 + b1), two N-halves =======
#pragma unroll 1
    for (int nh = 0; nh < 2; nh++) {
        zeroAcc();
        ldB(g_w1h + nh * 128, D_HID, 0);
        stB(0);
        __syncthreads();                       // (first iter also covers Aall)
#pragma unroll 1
        for (int ch = 0; ch < 4; ch++) {
            if (ch < 3) ldB(g_w1h + nh * 128, D_HID, ch + 1);
            mmaChunk(Aall + ch * 8192, ch & 1);
            if (ch < 3) stB((ch + 1) & 1);
            __syncthreads();
        }
        // epilogue: bias + relu, write fp16 into h1s in swizzled A-chunk layout
        int lrow = wm * 64 + (lane >> 2);
        int lcol = wn * 32 + (lane & 3) * 2;
#pragma unroll
        for (int i = 0; i < 4; i++) {
            int r0 = lrow + i * 16;
#pragma unroll
            for (int j = 0; j < 4; j++) {
                int gc = nh * 128 + lcol + j * 8;
                float bx = b1[gc], by = b1[gc + 1];
                __half2 v0 = __floats2half2_rn(fmaxf(acc[i][j][0] + bx, 0.f),
                                               fmaxf(acc[i][j][1] + by, 0.f));
                __half2 v1 = __floats2half2_rn(fmaxf(acc[i][j][2] + bx, 0.f),
                                               fmaxf(acc[i][j][3] + by, 0.f));
                int kc = gc >> 5, cp = gc & 31, c16 = cp >> 3, h = cp & 7;
                int r1 = r0 + 8;
                *(__half2*)(h1s + kc * 8192 + r0 * 64 +
                            ((c16 ^ ((r0 >> 1) & 3)) << 4) + h * 2) = v0;
                *(__half2*)(h1s + kc * 8192 + r1 * 64 +
                            ((c16 ^ ((r1 >> 1) & 3)) << 4) + h * 2) = v1;
            }
        }
        __syncthreads();
    }

    // ================= phase 2: y = dinv * (h1s @ W2) ========================
    zeroAcc();
    ldB(g_w2h, D_IN, 0);
    stB(0);
    __syncthreads();
#pragma unroll 1
    for (int ch = 0; ch < 8; ch++) {
        if (ch < 7) ldB(g_w2h, D_IN, ch + 1);
        mmaChunk(h1s + ch * 8192, ch & 1);
        if (ch < 7) stB((ch + 1) & 1);
        __syncthreads();
    }
    // epilogue: per-row dinv pre-scale, fp16 out to g_y
    int crow = rowBase + wm * 64 + (lane >> 2);
    int ccol = wn * 32 + (lane & 3) * 2;
#pragma unroll
    for (int i = 0; i < 4; i++) {
        int r0 = crow + i * 16;
        float dv0 = (r0 < NN)     ? g_dinv[r0]     : 0.f;
        float dv1 = (r0 + 8 < NN) ? g_dinv[r0 + 8] : 0.f;
#pragma unroll
        for (int j = 0; j < 4; j++) {
            int c0 = ccol + j * 8;
            *(__half2*)&g_y[(size_t)r0 * D_IN + c0] =
                __floats2half2_rn(acc[i][j][0] * dv0, acc[i][j][1] * dv0);
            *(__half2*)&g_y[(size_t)(r0 + 8) * D_IN + c0] =
                __floats2half2_rn(acc[i][j][2] * dv1, acc[i][j][3] * dv1);
        }
    }
}

// ---------------- launch (kernel launches ONLY) -----------------------------
extern "C" void kernel_launch(void* const* d_in, const int* in_sizes, int n_in,
                              void* d_out, int out_size) {
    const float* x     = (const float*)d_in[0];
    const int*   ei    = (const int*)d_in[1];      // int32 edge_index [2, NE]
    const float* W1    = (const float*)d_in[2];
    const float* b1    = (const float*)d_in[3];
    const float* W2    = (const float*)d_in[4];
    const float* b2    = (const float*)d_in[5];
    const float* gamma = (const float*)d_in[6];
    const float* beta  = (const float*)d_in[7];
    float* out = (float*)d_out;

    const int FUSED_SMEM = 114688;   // 112 KB -> 2 CTAs/SM
    cudaFuncSetAttribute(k_fused, cudaFuncAttributeMaxDynamicSharedMemorySize,
                         FUSED_SMEM);

    k_prep     <<<(NN + 255) / 256, 256>>>(W1, W2);
    k_hist     <<<(NE + 255) / 256, 256>>>(ei);
    k_scanfuse <<<98, 1024>>>();
    k_fillscale<<<(NN * 32 + 255) / 256, 256>>>(ei, x);

    // xa = A @ x  (unweighted fp16 gather of pre-scaled rows)
    k_agg1<<<(NN * 32) / 256, 256>>>();

    // y = dinv * (relu(xa @ W1 + b1) @ W2)   — fused double GEMM, h1 in SMEM
    k_fused<<<NTILES, 256, FUSED_SMEM>>>(b1);

    // out = LayerNorm(A @ y + b2)
    k_agg2<<<(NN * 32) / 256, 256>>>(out, b2, gamma, beta);
}

// round 16
// speedup vs baseline: 1.2675x; 1.0288x over previous
#include <cuda_runtime.h>
#include <cuda_fp16.h>
#include <cstdint>

#define NN   100000
#define NE   1600000
#define NPAD 100096          // 782 * 128
#define D_IN  128
#define D_HID 256
#define NTILES (NPAD / 128)  // 782
#define SCAN_FLAG 0x40000000

// ---------------- scratch (static __device__ arrays; device-code refs only) -
// g_cnt / g_bsum invariant: zero at entry of every kernel_launch sequence
// (zero-initialized at load; re-zeroed at the end of each sequence by
// k_fillscale, which runs after k_scanfuse has consumed them).
__device__ int   g_cnt[NN];
__device__ int   g_rowptr[NN + 1];
__device__ int   g_wp[NN];
__device__ int   g_col[NE];                    // src index only (rows pre-scaled)
__device__ float g_dinv[NN];
__device__ int   g_bsum[128];
__device__ __align__(16) __half g_xh [(size_t)NN   * D_IN];   // dinv*x fp16
__device__ __align__(16) __half g_xa [(size_t)NPAD * D_IN];   // A@x fp16
__device__ __align__(16) __half g_y  [(size_t)NPAD * D_IN];   // dinv*(h1@W2) fp16
__device__ __align__(16) __half g_w1h[D_IN * D_HID];
__device__ __align__(16) __half g_w2h[D_HID * D_IN];

// ---------------- fused weight-convert + degree histogram --------------------
__global__ void k_prephist(const float* __restrict__ W1,
                           const float* __restrict__ W2,
                           const int* __restrict__ ei) {
    int i = blockIdx.x * 256 + threadIdx.x;   // 0 .. NE-1 (1.6M)
    if (i < (D_IN * D_HID) / 4) {
        float4 a = ((const float4*)W1)[i];
        float4 b = ((const float4*)W2)[i];
        __half2 a0 = __floats2half2_rn(a.x, a.y), a1 = __floats2half2_rn(a.z, a.w);
        __half2 b0 = __floats2half2_rn(b.x, b.y), b1 = __floats2half2_rn(b.z, b.w);
        ((uint2*)g_w1h)[i] = make_uint2(*(uint32_t*)&a0, *(uint32_t*)&a1);
        ((uint2*)g_w2h)[i] = make_uint2(*(uint32_t*)&b0, *(uint32_t*)&b1);
    }
    atomicAdd(&g_cnt[ei[NE + i]], 1);         // g_cnt pre-zeroed (invariant)
}

// ---------------- single-pass scan + finalize (98 blocks, all resident) -----
__global__ void k_scanfuse() {
    __shared__ int sh[1024];
    __shared__ int s_base;
    int bid = blockIdx.x, tid = threadIdx.x;
    int i = bid * 1024 + tid;
    int v = (i < NN) ? g_cnt[i] : 0;
    sh[tid] = v;
    if (tid == 0) s_base = 0;
    __syncthreads();
    for (int off = 1; off < 1024; off <<= 1) {
        int t = (tid >= off) ? sh[tid - off] : 0;
        __syncthreads();
        sh[tid] += t;
        __syncthreads();
    }
    int incl = sh[tid];
    if (tid == 1023) atomicExch(&g_bsum[bid], sh[1023] | SCAN_FLAG);  // publish
    if (tid < bid) {                           // decoupled wait on predecessors
        int p;
        do { p = atomicAdd(&g_bsum[tid], 0); } while (!(p & SCAN_FLAG));
        atomicAdd(&s_base, p & ~SCAN_FLAG);
    }
    __syncthreads();
    if (i < NN) {
        int rp = (incl - v) + s_base;          // global exclusive prefix
        g_rowptr[i] = rp;
        g_wp[i] = rp;
        g_dinv[i] = rsqrtf((float)(v + 1));
    }
    if (i == 0) g_rowptr[NN] = NE;
}

// ---------------- fused CSR fill + x pre-scale (MLP-2, streaming) -----------
// grid: NE/256 = 6250 blocks. Each thread: 1 edge + 2 float4s of x.
// Also restores the g_cnt/g_bsum zero-invariant for the next replay.
__global__ void k_fillscale(const int* __restrict__ ei,
                            const float* __restrict__ x) {
    int gid = blockIdx.x * 256 + threadIdx.x;          // < NE
    int s = ei[gid];
    int d = ei[NE + gid];
    int pos = atomicAdd(&g_wp[d], 1);
    g_col[pos] = s;

    int i0 = blockIdx.x * 512 + threadIdx.x;           // coalesced pair
    int i1 = i0 + 256;                                 // i1 < NN*32 = 3.2M
    float4 v0 = __ldcs(((const float4*)x) + i0);       // streaming: evict-first
    float4 v1 = __ldcs(((const float4*)x) + i1);
    float dv0 = g_dinv[i0 >> 5];
    float dv1 = g_dinv[i1 >> 5];
    __half2 a0 = __floats2half2_rn(v0.x * dv0, v0.y * dv0);
    __half2 a1 = __floats2half2_rn(v0.z * dv0, v0.w * dv0);
    __half2 b0 = __floats2half2_rn(v1.x * dv1, v1.y * dv1);
    __half2 b1 = __floats2half2_rn(v1.z * dv1, v1.w * dv1);
    __stcs(((uint2*)g_xh) + i0, make_uint2(*(uint32_t*)&a0, *(uint32_t*)&a1));
    __stcs(((uint2*)g_xh) + i1, make_uint2(*(uint32_t*)&b0, *(uint32_t*)&b1));

    if (gid < NN)  g_cnt[gid] = 0;                     // restore invariant
    if (gid < 128) g_bsum[gid] = 0;
}

// ---------------- aggregation: unweighted row sum (rows pre-scaled) --------
__device__ __forceinline__ void add_row(float4& acc, uint2 raw) {
    float2 f0 = __half22float2(*(__half2*)&raw.x);
    float2 f1 = __half22float2(*(__half2*)&raw.y);
    acc.x += f0.x; acc.y += f0.y; acc.z += f1.x; acc.w += f1.y;
}

__device__ __forceinline__ float4 agg_row_h(const __half* __restrict__ X,
                                            int node, int lane) {
    const uint2* Xv = (const uint2*)X;
    float4 acc = make_float4(0.f, 0.f, 0.f, 0.f);
    int r0 = g_rowptr[node], r1 = g_rowptr[node + 1];

    for (int base = r0; base < r1; base += 32) {
        int n = r1 - base; if (n > 32) n = 32;
        int c = g_col[base + (lane < n ? lane : 0)];      // coalesced
        int t = 0;
#pragma unroll 1
        for (; t + 4 <= n; t += 4) {                      // MLP=4
            int s0 = __shfl_sync(0xffffffffu, c, t);
            int s1 = __shfl_sync(0xffffffffu, c, t + 1);
            int s2 = __shfl_sync(0xffffffffu, c, t + 2);
            int s3 = __shfl_sync(0xffffffffu, c, t + 3);
            uint2 q0 = Xv[(size_t)s0 * 32 + lane];
            uint2 q1 = Xv[(size_t)s1 * 32 + lane];
            uint2 q2 = Xv[(size_t)s2 * 32 + lane];
            uint2 q3 = Xv[(size_t)s3 * 32 + lane];
            add_row(acc, q0);
            add_row(acc, q1);
            add_row(acc, q2);
            add_row(acc, q3);
        }
#pragma unroll 1
        for (; t < n; t++) {
            int s = __shfl_sync(0xffffffffu, c, t);
            add_row(acc, Xv[(size_t)s * 32 + lane]);
        }
    }
    add_row(acc, Xv[(size_t)node * 32 + lane]);           // self-loop (pre-scaled)
    float di = g_dinv[node];
    acc.x *= di; acc.y *= di; acc.z *= di; acc.w *= di;
    return acc;
}

__global__ void k_agg1() {
    int gw   = (blockIdx.x * blockDim.x + threadIdx.x) >> 5;
    int lane = threadIdx.x & 31;
    if (gw >= NN) return;
    float4 a = agg_row_h(g_xh, gw, lane);
    __half2 h0 = __floats2half2_rn(a.x, a.y);
    __half2 h1 = __floats2half2_rn(a.z, a.w);
    ((uint2*)g_xa)[(size_t)gw * 32 + lane] =
        make_uint2(*(uint32_t*)&h0, *(uint32_t*)&h1);
}

__global__ void k_agg2(float* __restrict__ out,
                       const float* __restrict__ bias,
                       const float* __restrict__ gamma,
                       const float* __restrict__ beta) {
    int gw   = (blockIdx.x * blockDim.x + threadIdx.x) >> 5;
    int lane = threadIdx.x & 31;
    if (gw >= NN) return;
    float4 acc = agg_row_h(g_y, gw, lane);

    float4 bb = ((const float4*)bias)[lane];
    acc.x += bb.x; acc.y += bb.y; acc.z += bb.z; acc.w += bb.w;

    float s = acc.x + acc.y + acc.z + acc.w;
#pragma unroll
    for (int o = 16; o; o >>= 1) s += __shfl_xor_sync(0xffffffffu, s, o);
    float mu = s * (1.f / 128.f);

    float d0 = acc.x - mu, d1 = acc.y - mu, d2 = acc.z - mu, d3 = acc.w - mu;
    float ss = d0 * d0 + d1 * d1 + d2 * d2 + d3 * d3;
#pragma unroll
    for (int o = 16; o; o >>= 1) ss += __shfl_xor_sync(0xffffffffu, ss, o);
    float rs = rsqrtf(ss * (1.f / 128.f) + 1e-5f);

    float4 g  = ((const float4*)gamma)[lane];
    float4 be = ((const float4*)beta)[lane];
    float4 o4;
    o4.x = d0 * rs * g.x + be.x;
    o4.y = d1 * rs * g.y + be.y;
    o4.z = d2 * rs * g.z + be.z;
    o4.w = d3 * rs * g.w + be.w;
    ((float4*)out)[(size_t)gw * 32 + lane] = o4;
}

// ---------------- fused double GEMM: y = dinv*(relu(xa@W1+b1)@W2) ------------
__device__ __forceinline__ uint32_t smem_u32(const void* p) {
    uint32_t a;
    asm("{ .reg .u64 t; cvta.to.shared.u64 t, %1; cvt.u32.u64 %0, t; }"
        : "=r"(a) : "l"(p));
    return a;
}
__device__ __forceinline__ void ldsm_x4(uint32_t* r, uint32_t addr) {
    asm volatile("ldmatrix.sync.aligned.m8n8.x4.shared.b16 {%0,%1,%2,%3}, [%4];"
        : "=r"(r[0]), "=r"(r[1]), "=r"(r[2]), "=r"(r[3]) : "r"(addr));
}
__device__ __forceinline__ void ldsm_x2t(uint32_t* r, uint32_t addr) {
    asm volatile("ldmatrix.sync.aligned.m8n8.x2.trans.shared.b16 {%0,%1}, [%2];"
        : "=r"(r[0]), "=r"(r[1]) : "r"(addr));
}
__device__ __forceinline__ void mma_f16(float* c, const uint32_t* a, const uint32_t* b) {
    asm volatile(
        "mma.sync.aligned.m16n8k16.row.col.f32.f16.f16.f32 "
        "{%0,%1,%2,%3}, {%4,%5,%6,%7}, {%8,%9}, {%0,%1,%2,%3};"
        : "+f"(c[0]), "+f"(c[1]), "+f"(c[2]), "+f"(c[3])
        : "r"(a[0]), "r"(a[1]), "r"(a[2]), "r"(a[3]), "r"(b[0]), "r"(b[1]));
}

// SMEM layout (dynamic, 114688 B):
//   h1s  [0      .. 65536)  : h1 tile 128x256 fp16 as 8 swizzled A-chunks (8KB each)
//   Aall [65536  .. 98304)  : xa tile 128x128 fp16 as 4 swizzled A-chunks
//   Bsm  [98304  .. 114688) : 2 x 8KB B staging (32 k-rows x 128 cols)
__global__ __launch_bounds__(256)
void k_fused(const float* __restrict__ b1) {
    extern __shared__ __align__(16) char sm[];
    char* h1s  = sm;
    char* Aall = sm + 65536;
    char* BsmP[2] = {sm + 98304, sm + 106496};

    int tid = threadIdx.x, wid = tid >> 5, lane = tid & 31;
    int wm = wid >> 2, wn = wid & 3;          // 2x4 warps, 64x32 warp tile
    int rowBase = blockIdx.x * 128;

    // ---- stage full A tile (g_xa) into Aall: 4 chunks, swizzled ----
#pragma unroll
    for (int ch = 0; ch < 4; ch++) {
#pragma unroll
        for (int it = 0; it < 2; it++) {
            int u = tid + it * 256;
            int r = u >> 2, c16 = u & 3;
            uint4 v = *(const uint4*)(g_xa + (size_t)(rowBase + r) * D_IN + ch * 32 + c16 * 8);
            *(uint4*)(Aall + ch * 8192 + r * 64 + ((c16 ^ ((r >> 1) & 3)) << 4)) = v;
        }
    }

    uint4 sb[2];
    auto ldB = [&](const __half* Bb, int NT, int ch) {
#pragma unroll
        for (int it = 0; it < 2; it++) {
            int u = tid + it * 256;
            sb[it] = *(const uint4*)(Bb + (size_t)(ch * 32 + (u >> 4)) * NT + (u & 15) * 8);
        }
    };
    auto stB = [&](int buf) {
#pragma unroll
        for (int it = 0; it < 2; it++) {
            int u = tid + it * 256;
            int k = u >> 4, d16 = u & 15;
            *(uint4*)(BsmP[buf] + k * 256 + ((d16 ^ (k & 7)) << 4)) = sb[it];
        }
    };

    int aG  = lane >> 3;
    int aRl = (aG & 1) * 8 + (lane & 7);
    int aCo = aG >> 1;
    int bK  = lane & 15;

    float acc[4][4][4];
    auto zeroAcc = [&]() {
#pragma unroll
        for (int i = 0; i < 4; i++)
#pragma unroll
            for (int j = 0; j < 4; j++)
#pragma unroll
                for (int q = 0; q < 4; q++) acc[i][j][q] = 0.f;
    };
    auto mmaChunk = [&](const char* aChunk, int buf) {
        uint32_t aBase = smem_u32(aChunk);
        uint32_t bBase = smem_u32(BsmP[buf]);
#pragma unroll
        for (int ks = 0; ks < 2; ks++) {
            uint32_t af[4][4], bf[4][2];
#pragma unroll
            for (int i = 0; i < 4; i++) {
                int r   = (wm * 4 + i) * 16 + aRl;
                int c16 = ks * 2 + aCo;
                ldsm_x4(af[i], aBase + r * 64 + ((c16 ^ ((r >> 1) & 3)) << 4));
            }
#pragma unroll
            for (int j = 0; j < 4; j++) {
                int ntile = wn * 4 + j;
                int k = ks * 16 + bK;
                ldsm_x2t(bf[j], bBase + k * 256 + ((ntile ^ (k & 7)) << 4));
            }
#pragma unroll
            for (int i = 0; i < 4; i++)
#pragma unroll
                for (int j = 0; j < 4; j++)
                    mma_f16(acc[i][j], af[i], bf[j]);
        }
    };

    // ================= phase 1: h1 = relu(xa @ W1 + b1), two N-halves =======
#pragma unroll 1
    for (int nh = 0; nh < 2; nh++) {
        zeroAcc();
        ldB(g_w1h + nh * 128, D_HID, 0);
        stB(0);
        __syncthreads();                       // (first iter also covers Aall)
#pragma unroll 1
        for (int ch = 0; ch < 4; ch++) {
            if (ch < 3) ldB(g_w1h + nh * 128, D_HID, ch + 1);
            mmaChunk(Aall + ch * 8192, ch & 1);
            if (ch < 3) stB((ch + 1) & 1);
            __syncthreads();
        }
        // epilogue: bias + relu, write fp16 into h1s in swizzled A-chunk layout
        int lrow = wm * 64 + (lane >> 2);
        int lcol = wn * 32 + (lane & 3) * 2;
#pragma unroll
        for (int i = 0; i < 4; i++) {
            int r0 = lrow + i * 16;
#pragma unroll
            for (int j = 0; j < 4; j++) {
                int gc = nh * 128 + lcol + j * 8;
                float bx = b1[gc], by = b1[gc + 1];
                __half2 v0 = __floats2half2_rn(fmaxf(acc[i][j][0] + bx, 0.f),
                                               fmaxf(acc[i][j][1] + by, 0.f));
                __half2 v1 = __floats2half2_rn(fmaxf(acc[i][j][2] + bx, 0.f),
                                               fmaxf(acc[i][j][3] + by, 0.f));
                int kc = gc >> 5, cp = gc & 31, c16 = cp >> 3, h = cp & 7;
                int r1 = r0 + 8;
                *(__half2*)(h1s + kc * 8192 + r0 * 64 +
                            ((c16 ^ ((r0 >> 1) & 3)) << 4) + h * 2) = v0;
                *(__half2*)(h1s + kc * 8192 + r1 * 64 +
                            ((c16 ^ ((r1 >> 1) & 3)) << 4) + h * 2) = v1;
            }
        }
        __syncthreads();
    }

    // ================= phase 2: y = dinv * (h1s @ W2) ========================
    zeroAcc();
    ldB(g_w2h, D_IN, 0);
    stB(0);
    __syncthreads();
#pragma unroll 1
    for (int ch = 0; ch < 8; ch++) {
        if (ch < 7) ldB(g_w2h, D_IN, ch + 1);
        mmaChunk(h1s + ch * 8192, ch & 1);
        if (ch < 7) stB((ch + 1) & 1);
        __syncthreads();
    }
    // epilogue: per-row dinv pre-scale, fp16 out to g_y
    int crow = rowBase + wm * 64 + (lane >> 2);
    int ccol = wn * 32 + (lane & 3) * 2;
#pragma unroll
    for (int i = 0; i < 4; i++) {
        int r0 = crow + i * 16;
        float dv0 = (r0 < NN)     ? g_dinv[r0]     : 0.f;
        float dv1 = (r0 + 8 < NN) ? g_dinv[r0 + 8] : 0.f;
#pragma unroll
        for (int j = 0; j < 4; j++) {
            int c0 = ccol + j * 8;
            *(__half2*)&g_y[(size_t)r0 * D_IN + c0] =
                __floats2half2_rn(acc[i][j][0] * dv0, acc[i][j][1] * dv0);
            *(__half2*)&g_y[(size_t)(r0 + 8) * D_IN + c0] =
                __floats2half2_rn(acc[i][j][2] * dv1, acc[i][j][3] * dv1);
        }
    }
}

// ---------------- launch (kernel launches ONLY) -----------------------------
extern "C" void kernel_launch(void* const* d_in, const int* in_sizes, int n_in,
                              void* d_out, int out_size) {
    const float* x     = (const float*)d_in[0];
    const int*   ei    = (const int*)d_in[1];      // int32 edge_index [2, NE]
    const float* W1    = (const float*)d_in[2];
    const float* b1    = (const float*)d_in[3];
    const float* W2    = (const float*)d_in[4];
    const float* b2    = (const float*)d_in[5];
    const float* gamma = (const float*)d_in[6];
    const float* beta  = (const float*)d_in[7];
    float* out = (float*)d_out;

    const int FUSED_SMEM = 114688;   // 112 KB -> 2 CTAs/SM
    cudaFuncSetAttribute(k_fused, cudaFuncAttributeMaxDynamicSharedMemorySize,
                         FUSED_SMEM);

    k_prephist <<<NE / 256, 256>>>(W1, W2, ei);
    k_scanfuse <<<98, 1024>>>();
    k_fillscale<<<NE / 256, 256>>>(ei, x);

    // xa = A @ x  (unweighted fp16 gather of pre-scaled rows)
    k_agg1<<<(NN * 32) / 256, 256>>>();

    // y = dinv * (relu(xa @ W1 + b1) @ W2)   — fused double GEMM, h1 in SMEM
    k_fused<<<NTILES, 256, FUSED_SMEM>>>(b1);

    // out = LayerNorm(A @ y + b2)
    k_agg2<<<(NN * 32) / 256, 256>>>(out, b2, gamma, beta);
}

// round 17
// speedup vs baseline: 1.2913x; 1.0188x over previous
#include <cuda_runtime.h>
#include <cuda_fp16.h>
#include <cstdint>

#define NN   100000
#define NE   1600000
#define NPAD 100096          // 782 * 128
#define D_IN  128
#define D_HID 256
#define NTILES (NPAD / 128)  // 782
#define SCAN_FLAG 0x40000000

// ---------------- scratch (static __device__ arrays; device-code refs only) -
// g_cnt / g_bsum invariant: zero at entry of every kernel_launch sequence
// (zero-initialized at load; re-zeroed at the end of each sequence by
// k_fillscale, which runs after k_scanfuse has consumed them).
__device__ int   g_cnt[NN];
__device__ int   g_rowptr[NN + 1];
__device__ int   g_wp[NN];
__device__ int   g_col[NE];                    // src index only (rows pre-scaled)
__device__ float g_dinv[NN];
__device__ int   g_bsum[128];
__device__ __align__(16) __half g_xh [(size_t)NN   * D_IN];   // dinv*x fp16
__device__ __align__(16) __half g_xa [(size_t)NPAD * D_IN];   // A@x fp16
__device__ __align__(16) __half g_y  [(size_t)NPAD * D_IN];   // dinv*(h1@W2) fp16
__device__ __align__(16) __half g_w1h[D_IN * D_HID];
__device__ __align__(16) __half g_w2h[D_HID * D_IN];

// ---------------- fused weight-convert + degree histogram --------------------
__global__ void k_prephist(const float* __restrict__ W1,
                           const float* __restrict__ W2,
                           const int* __restrict__ ei) {
    int i = blockIdx.x * 256 + threadIdx.x;   // 0 .. NE-1 (1.6M)
    if (i < (D_IN * D_HID) / 4) {
        float4 a = ((const float4*)W1)[i];
        float4 b = ((const float4*)W2)[i];
        __half2 a0 = __floats2half2_rn(a.x, a.y), a1 = __floats2half2_rn(a.z, a.w);
        __half2 b0 = __floats2half2_rn(b.x, b.y), b1 = __floats2half2_rn(b.z, b.w);
        ((uint2*)g_w1h)[i] = make_uint2(*(uint32_t*)&a0, *(uint32_t*)&a1);
        ((uint2*)g_w2h)[i] = make_uint2(*(uint32_t*)&b0, *(uint32_t*)&b1);
    }
    atomicAdd(&g_cnt[ei[NE + i]], 1);         // g_cnt pre-zeroed (invariant)
}

// ---------------- single-pass scan + finalize (98 blocks, all resident) -----
__global__ void k_scanfuse() {
    __shared__ int sh[1024];
    __shared__ int s_base;
    int bid = blockIdx.x, tid = threadIdx.x;
    int i = bid * 1024 + tid;
    int v = (i < NN) ? g_cnt[i] : 0;
    sh[tid] = v;
    if (tid == 0) s_base = 0;
    __syncthreads();
    for (int off = 1; off < 1024; off <<= 1) {
        int t = (tid >= off) ? sh[tid - off] : 0;
        __syncthreads();
        sh[tid] += t;
        __syncthreads();
    }
    int incl = sh[tid];
    if (tid == 1023) atomicExch(&g_bsum[bid], sh[1023] | SCAN_FLAG);  // publish
    if (tid < bid) {                           // decoupled wait on predecessors
        int p;
        do { p = atomicAdd(&g_bsum[tid], 0); } while (!(p & SCAN_FLAG));
        atomicAdd(&s_base, p & ~SCAN_FLAG);
    }
    __syncthreads();
    if (i < NN) {
        int rp = (incl - v) + s_base;          // global exclusive prefix
        g_rowptr[i] = rp;
        g_wp[i] = rp;
        g_dinv[i] = rsqrtf((float)(v + 1));
    }
    if (i == 0) g_rowptr[NN] = NE;
}

// ---------------- fused CSR fill + x pre-scale (MLP-2, streaming) -----------
__global__ void k_fillscale(const int* __restrict__ ei,
                            const float* __restrict__ x) {
    int gid = blockIdx.x * 256 + threadIdx.x;          // < NE
    int s = ei[gid];
    int d = ei[NE + gid];
    int pos = atomicAdd(&g_wp[d], 1);
    g_col[pos] = s;

    int i0 = blockIdx.x * 512 + threadIdx.x;           // coalesced pair
    int i1 = i0 + 256;                                 // i1 < NN*32 = 3.2M
    float4 v0 = __ldcs(((const float4*)x) + i0);       // streaming: evict-first
    float4 v1 = __ldcs(((const float4*)x) + i1);
    float dv0 = g_dinv[i0 >> 5];
    float dv1 = g_dinv[i1 >> 5];
    __half2 a0 = __floats2half2_rn(v0.x * dv0, v0.y * dv0);
    __half2 a1 = __floats2half2_rn(v0.z * dv0, v0.w * dv0);
    __half2 b0 = __floats2half2_rn(v1.x * dv1, v1.y * dv1);
    __half2 b1 = __floats2half2_rn(v1.z * dv1, v1.w * dv1);
    __stcs(((uint2*)g_xh) + i0, make_uint2(*(uint32_t*)&a0, *(uint32_t*)&a1));
    __stcs(((uint2*)g_xh) + i1, make_uint2(*(uint32_t*)&b0, *(uint32_t*)&b1));

    if (gid < NN)  g_cnt[gid] = 0;                     // restore invariant
    if (gid < 128) g_bsum[gid] = 0;
}

// ---------------- aggregation: pairwise fp16 tree, fp32 accumulators --------
__device__ __forceinline__ __half2 u2h(uint32_t u) { return *(__half2*)&u; }

__device__ __forceinline__ float4 agg_row_h(const __half* __restrict__ X,
                                            int node, int lane) {
    const uint2* Xv = (const uint2*)X;
    float4 acc = make_float4(0.f, 0.f, 0.f, 0.f);
    int r0 = g_rowptr[node], r1 = g_rowptr[node + 1];

    for (int base = r0; base < r1; base += 32) {
        int n = r1 - base; if (n > 32) n = 32;
        int c = g_col[base + (lane < n ? lane : 0)];      // coalesced
        int t = 0;
#pragma unroll 1
        for (; t + 4 <= n; t += 4) {                      // MLP=4, fp16 tree
            int s0 = __shfl_sync(0xffffffffu, c, t);
            int s1 = __shfl_sync(0xffffffffu, c, t + 1);
            int s2 = __shfl_sync(0xffffffffu, c, t + 2);
            int s3 = __shfl_sync(0xffffffffu, c, t + 3);
            uint2 q0 = Xv[(size_t)s0 * 32 + lane];
            uint2 q1 = Xv[(size_t)s1 * 32 + lane];
            uint2 q2 = Xv[(size_t)s2 * 32 + lane];
            uint2 q3 = Xv[(size_t)s3 * 32 + lane];
            // 2-level half2 tree: 6 HADD2 replaces 16 cvt+FADD
            __half2 a01 = __hadd2(u2h(q0.x), u2h(q1.x));
            __half2 b01 = __hadd2(u2h(q0.y), u2h(q1.y));
            __half2 a23 = __hadd2(u2h(q2.x), u2h(q3.x));
            __half2 b23 = __hadd2(u2h(q2.y), u2h(q3.y));
            __half2 a = __hadd2(a01, a23);
            __half2 b = __hadd2(b01, b23);
            float2 fa = __half22float2(a);
            float2 fb = __half22float2(b);
            acc.x += fa.x; acc.y += fa.y;
            acc.z += fb.x; acc.w += fb.y;
        }
#pragma unroll 1
        for (; t < n; t++) {                              // fp32 remainder
            int s = __shfl_sync(0xffffffffu, c, t);
            uint2 q = Xv[(size_t)s * 32 + lane];
            float2 f0 = __half22float2(u2h(q.x));
            float2 f1 = __half22float2(u2h(q.y));
            acc.x += f0.x; acc.y += f0.y;
            acc.z += f1.x; acc.w += f1.y;
        }
    }
    {   // self-loop (pre-scaled), fp32
        uint2 q = Xv[(size_t)node * 32 + lane];
        float2 f0 = __half22float2(u2h(q.x));
        float2 f1 = __half22float2(u2h(q.y));
        acc.x += f0.x; acc.y += f0.y;
        acc.z += f1.x; acc.w += f1.y;
    }
    float di = g_dinv[node];
    acc.x *= di; acc.y *= di; acc.z *= di; acc.w *= di;
    return acc;
}

__global__ void k_agg1() {
    int gw   = (blockIdx.x * blockDim.x + threadIdx.x) >> 5;
    int lane = threadIdx.x & 31;
    if (gw >= NN) return;
    float4 a = agg_row_h(g_xh, gw, lane);
    __half2 h0 = __floats2half2_rn(a.x, a.y);
    __half2 h1 = __floats2half2_rn(a.z, a.w);
    ((uint2*)g_xa)[(size_t)gw * 32 + lane] =
        make_uint2(*(uint32_t*)&h0, *(uint32_t*)&h1);
}

__global__ void k_agg2(float* __restrict__ out,
                       const float* __restrict__ bias,
                       const float* __restrict__ gamma,
                       const float* __restrict__ beta) {
    int gw   = (blockIdx.x * blockDim.x + threadIdx.x) >> 5;
    int lane = threadIdx.x & 31;
    if (gw >= NN) return;
    float4 acc = agg_row_h(g_y, gw, lane);

    float4 bb = ((const float4*)bias)[lane];
    acc.x += bb.x; acc.y += bb.y; acc.z += bb.z; acc.w += bb.w;

    float s = acc.x + acc.y + acc.z + acc.w;
#pragma unroll
    for (int o = 16; o; o >>= 1) s += __shfl_xor_sync(0xffffffffu, s, o);
    float mu = s * (1.f / 128.f);

    float d0 = acc.x - mu, d1 = acc.y - mu, d2 = acc.z - mu, d3 = acc.w - mu;
    float ss = d0 * d0 + d1 * d1 + d2 * d2 + d3 * d3;
#pragma unroll
    for (int o = 16; o; o >>= 1) ss += __shfl_xor_sync(0xffffffffu, ss, o);
    float rs = rsqrtf(ss * (1.f / 128.f) + 1e-5f);

    float4 g  = ((const float4*)gamma)[lane];
    float4 be = ((const float4*)beta)[lane];
    float4 o4;
    o4.x = d0 * rs * g.x + be.x;
    o4.y = d1 * rs * g.y + be.y;
    o4.z = d2 * rs * g.z + be.z;
    o4.w = d3 * rs * g.w + be.w;
    ((float4*)out)[(size_t)gw * 32 + lane] = o4;
}

// ---------------- fused double GEMM: y = dinv*(relu(xa@W1+b1)@W2) ------------
__device__ __forceinline__ uint32_t smem_u32(const void* p) {
    uint32_t a;
    asm("{ .reg .u64 t; cvta.to.shared.u64 t, %1; cvt.u32.u64 %0, t; }"
        : "=r"(a) : "l"(p));
    return a;
}
__device__ __forceinline__ void ldsm_x4(uint32_t* r, uint32_t addr) {
    asm volatile("ldmatrix.sync.aligned.m8n8.x4.shared.b16 {%0,%1,%2,%3}, [%4];"
        : "=r"(r[0]), "=r"(r[1]), "=r"(r[2]), "=r"(r[3]) : "r"(addr));
}
__device__ __forceinline__ void ldsm_x2t(uint32_t* r, uint32_t addr) {
    asm volatile("ldmatrix.sync.aligned.m8n8.x2.trans.shared.b16 {%0,%1}, [%2];"
        : "=r"(r[0]), "=r"(r[1]) : "r"(addr));
}
__device__ __forceinline__ void mma_f16(float* c, const uint32_t* a, const uint32_t* b) {
    asm volatile(
        "mma.sync.aligned.m16n8k16.row.col.f32.f16.f16.f32 "
        "{%0,%1,%2,%3}, {%4,%5,%6,%7}, {%8,%9}, {%0,%1,%2,%3};"
        : "+f"(c[0]), "+f"(c[1]), "+f"(c[2]), "+f"(c[3])
        : "r"(a[0]), "r"(a[1]), "r"(a[2]), "r"(a[3]), "r"(b[0]), "r"(b[1]));
}

// SMEM layout (dynamic, 114688 B):
//   h1s  [0      .. 65536)  : h1 tile 128x256 fp16 as 8 swizzled A-chunks (8KB each)
//   Aall [65536  .. 98304)  : xa tile 128x128 fp16 as 4 swizzled A-chunks
//   Bsm  [98304  .. 114688) : 2 x 8KB B staging (32 k-rows x 128 cols)
__global__ __launch_bounds__(256)
void k_fused(const float* __restrict__ b1) {
    extern __shared__ __align__(16) char sm[];
    char* h1s  = sm;
    char* Aall = sm + 65536;
    char* BsmP[2] = {sm + 98304, sm + 106496};

    int tid = threadIdx.x, wid = tid >> 5, lane = tid & 31;
    int wm = wid >> 2, wn = wid & 3;          // 2x4 warps, 64x32 warp tile
    int rowBase = blockIdx.x * 128;

    // ---- stage full A tile (g_xa) into Aall: 4 chunks, swizzled ----
#pragma unroll
    for (int ch = 0; ch < 4; ch++) {
#pragma unroll
        for (int it = 0; it < 2; it++) {
            int u = tid + it * 256;
            int r = u >> 2, c16 = u & 3;
            uint4 v = *(const uint4*)(g_xa + (size_t)(rowBase + r) * D_IN + ch * 32 + c16 * 8);
            *(uint4*)(Aall + ch * 8192 + r * 64 + ((c16 ^ ((r >> 1) & 3)) << 4)) = v;
        }
    }

    uint4 sb[2];
    auto ldB = [&](const __half* Bb, int NT, int ch) {
#pragma unroll
        for (int it = 0; it < 2; it++) {
            int u = tid + it * 256;
            sb[it] = *(const uint4*)(Bb + (size_t)(ch * 32 + (u >> 4)) * NT + (u & 15) * 8);
        }
    };
    auto stB = [&](int buf) {
#pragma unroll
        for (int it = 0; it < 2; it++) {
            int u = tid + it * 256;
            int k = u >> 4, d16 = u & 15;
            *(uint4*)(BsmP[buf] + k * 256 + ((d16 ^ (k & 7)) << 4)) = sb[it];
        }
    };

    int aG  = lane >> 3;
    int aRl = (aG & 1) * 8 + (lane & 7);
    int aCo = aG >> 1;
    int bK  = lane & 15;

    float acc[4][4][4];
    auto zeroAcc = [&]() {
#pragma unroll
        for (int i = 0; i < 4; i++)
#pragma unroll
            for (int j = 0; j < 4; j++)
#pragma unroll
                for (int q = 0; q < 4; q++) acc[i][j][q] = 0.f;
    };
    auto mmaChunk = [&](const char* aChunk, int buf) {
        uint32_t aBase = smem_u32(aChunk);
        uint32_t bBase = smem_u32(BsmP[buf]);
#pragma unroll
        for (int ks = 0; ks < 2; ks++) {
            uint32_t af[4][4], bf[4][2];
#pragma unroll
            for (int i = 0; i < 4; i++) {
                int r   = (wm * 4 + i) * 16 + aRl;
                int c16 = ks * 2 + aCo;
                ldsm_x4(af[i], aBase + r * 64 + ((c16 ^ ((r >> 1) & 3)) << 4));
            }
#pragma unroll
            for (int j = 0; j < 4; j++) {
                int ntile = wn * 4 + j;
                int k = ks * 16 + bK;
                ldsm_x2t(bf[j], bBase + k * 256 + ((ntile ^ (k & 7)) << 4));
            }
#pragma unroll
            for (int i = 0; i < 4; i++)
#pragma unroll
                for (int j = 0; j < 4; j++)
                    mma_f16(acc[i][j], af[i], bf[j]);
        }
    };

    // ================= phase 1: h1 = relu(xa @ W1 + b1), two N-halves =======
#pragma unroll 1
    for (int nh = 0; nh < 2; nh++) {
        zeroAcc();
        ldB(g_w1h + nh * 128, D_HID, 0);
        stB(0);
        __syncthreads();                       // (first iter also covers Aall)
#pragma unroll 1
        for (int ch = 0; ch < 4; ch++) {
            if (ch < 3) ldB(g_w1h + nh * 128, D_HID, ch + 1);
            mmaChunk(Aall + ch * 8192, ch & 1);
            if (ch < 3) stB((ch + 1) & 1);
            __syncthreads();
        }
        // epilogue: bias + relu, write fp16 into h1s in swizzled A-chunk layout
        int lrow = wm * 64 + (lane >> 2);
        int lcol = wn * 32 + (lane & 3) * 2;
#pragma unroll
        for (int i = 0; i < 4; i++) {
            int r0 = lrow + i * 16;
#pragma unroll
            for (int j = 0; j < 4; j++) {
                int gc = nh * 128 + lcol + j * 8;
                float bx = b1[gc], by = b1[gc + 1];
                __half2 v0 = __floats2half2_rn(fmaxf(acc[i][j][0] + bx, 0.f),
                                               fmaxf(acc[i][j][1] + by, 0.f));
                __half2 v1 = __floats2half2_rn(fmaxf(acc[i][j][2] + bx, 0.f),
                                               fmaxf(acc[i][j][3] + by, 0.f));
                int kc = gc >> 5, cp = gc & 31, c16 = cp >> 3, h = cp & 7;
                int r1 = r0 + 8;
                *(__half2*)(h1s + kc * 8192 + r0 * 64 +
                            ((c16 ^ ((r0 >> 1) & 3)) << 4) + h * 2) = v0;
                *(__half2*)(h1s + kc * 8192 + r1 * 64 +
                            ((c16 ^ ((r1 >> 1) & 3)) << 4) + h * 2) = v1;
            }
        }
        __syncthreads();
    }

    // ================= phase 2: y = dinv * (h1s @ W2) ========================
    zeroAcc();
    ldB(g_w2h, D_IN, 0);
    stB(0);
    __syncthreads();
#pragma unroll 1
    for (int ch = 0; ch < 8; ch++) {
        if (ch < 7) ldB(g_w2h, D_IN, ch + 1);
        mmaChunk(h1s + ch * 8192, ch & 1);
        if (ch < 7) stB((ch + 1) & 1);
        __syncthreads();
    }
    // epilogue: per-row dinv pre-scale, fp16 out to g_y
    int crow = rowBase + wm * 64 + (lane >> 2);
    int ccol = wn * 32 + (lane & 3) * 2;
#pragma unroll
    for (int i = 0; i < 4; i++) {
        int r0 = crow + i * 16;
        float dv0 = (r0 < NN)     ? g_dinv[r0]     : 0.f;
        float dv1 = (r0 + 8 < NN) ? g_dinv[r0 + 8] : 0.f;
#pragma unroll
        for (int j = 0; j < 4; j++) {
            int c0 = ccol + j * 8;
            *(__half2*)&g_y[(size_t)r0 * D_IN + c0] =
                __floats2half2_rn(acc[i][j][0] * dv0, acc[i][j][1] * dv0);
            *(__half2*)&g_y[(size_t)(r0 + 8) * D_IN + c0] =
                __floats2half2_rn(acc[i][j][2] * dv1, acc[i][j][3] * dv1);
        }
    }
}

// ---------------- launch (kernel launches ONLY) -----------------------------
extern "C" void kernel_launch(void* const* d_in, const int* in_sizes, int n_in,
                              void* d_out, int out_size) {
    const float* x     = (const float*)d_in[0];
    const int*   ei    = (const int*)d_in[1];      // int32 edge_index [2, NE]
    const float* W1    = (const float*)d_in[2];
    const float* b1    = (const float*)d_in[3];
    const float* W2    = (const float*)d_in[4];
    const float* b2    = (const float*)d_in[5];
    const float* gamma = (const float*)d_in[6];
    const float* beta  = (const float*)d_in[7];
    float* out = (float*)d_out;

    const int FUSED_SMEM = 114688;   // 112 KB -> 2 CTAs/SM
    cudaFuncSetAttribute(k_fused, cudaFuncAttributeMaxDynamicSharedMemorySize,
                         FUSED_SMEM);

    k_prephist <<<NE / 256, 256>>>(W1, W2, ei);
    k_scanfuse <<<98, 1024>>>();
    k_fillscale<<<NE / 256, 256>>>(ei, x);

    // xa = A @ x  (fp16 pairwise-tree gather)
    k_agg1<<<(NN * 32) / 256, 256>>>();

    // y = dinv * (relu(xa @ W1 + b1) @ W2)   — fused double GEMM, h1 in SMEM
    k_fused<<<NTILES, 256, FUSED_SMEM>>>(b1);

    // out = LayerNorm(A @ y + b2)
    k_agg2<<<(NN * 32) / 256, 256>>>(out, b2, gamma, beta);
}